// round 13
// baseline (speedup 1.0000x reference)
#include <cuda_runtime.h>
#include <cuda_bf16.h>
#include <cstdint>
#include <math.h>

#define B_  64
#define T_  256
#define C_  256
#define H_  8
#define HS_ 32
#define L_  6
#define V_  96
#define BT_ (B_ * T_)
#define EPS_ 1e-5f

__device__ __align__(16) float g_x  [BT_ * C_];
__device__ __align__(16) float g_qkv[3 * BT_ * C_];
__device__ __align__(16) float g_nll[BT_];

__device__ __align__(16) __nv_bfloat16 g_xh [BT_ * C_];
__device__ __align__(16) __nv_bfloat16 g_xl [BT_ * C_];
__device__ __align__(16) __nv_bfloat16 g_ah [BT_ * C_];
__device__ __align__(16) __nv_bfloat16 g_al [BT_ * C_];
__device__ __align__(16) __nv_bfloat16 g_hh [BT_ * C_];
__device__ __align__(16) __nv_bfloat16 g_hl [BT_ * C_];

#define WMAT_ELEMS (C_ * C_)
#define WLM_ROWS   128
#define W_TOTAL    (36 * WMAT_ELEMS + WLM_ROWS * C_)
__device__ __align__(16) __nv_bfloat16 g_wh[W_TOTAL];
__device__ __align__(16) __nv_bfloat16 g_wl[W_TOTAL];
#define WOFF(t, l) ((size_t)((t) * 6 + (l)) * WMAT_ELEMS)
#define WOFF_LM    ((size_t)36 * WMAT_ELEMS)

// ---------------- helpers ----------------
__device__ __forceinline__ uint32_t smem_u32(const void* p) {
    uint32_t a;
    asm("{ .reg .u64 t; cvta.to.shared.u64 t, %1; cvt.u32.u64 %0, t; }" : "=r"(a) : "l"(p));
    return a;
}
__device__ __forceinline__ void cp_async16(uint32_t dst, const void* src) {
    asm volatile("cp.async.cg.shared.global [%0], [%1], 16;" :: "r"(dst), "l"(src) : "memory");
}
__device__ __forceinline__ void cp_commit() { asm volatile("cp.async.commit_group;" ::: "memory"); }
template <int N>
__device__ __forceinline__ void cp_wait() {
    asm volatile("cp.async.wait_group %0;" :: "n"(N) : "memory");
}
__device__ __forceinline__ void ldmatrix_x4(uint32_t* r, uint32_t addr) {
    asm volatile("ldmatrix.sync.aligned.m8n8.x4.shared.b16 {%0,%1,%2,%3}, [%4];"
                 : "=r"(r[0]), "=r"(r[1]), "=r"(r[2]), "=r"(r[3]) : "r"(addr));
}
__device__ __forceinline__ void mma16816(float* c, const uint32_t* a, const uint32_t* b) {
    asm volatile("mma.sync.aligned.m16n8k16.row.col.f32.bf16.bf16.f32 "
                 "{%0,%1,%2,%3}, {%4,%5,%6,%7}, {%8,%9}, {%0,%1,%2,%3};"
                 : "+f"(c[0]), "+f"(c[1]), "+f"(c[2]), "+f"(c[3])
                 : "r"(a[0]), "r"(a[1]), "r"(a[2]), "r"(a[3]), "r"(b[0]), "r"(b[1]));
}
__device__ __forceinline__ uint32_t packbf2(float a, float b) {
    __nv_bfloat162 t(__float2bfloat16(a), __float2bfloat16(b));
    return *(uint32_t*)&t;
}

// ---------------- weight transpose + hi/lo ----------------
__global__ void convw_all(const float* __restrict__ Wq, const float* __restrict__ Wk,
                          const float* __restrict__ Wv, const float* __restrict__ Wo,
                          const float* __restrict__ W1, const float* __restrict__ W2,
                          const float* __restrict__ Wlm,
                          __nv_bfloat16* __restrict__ hi, __nv_bfloat16* __restrict__ lo) {
    const int mat = blockIdx.y;
    const int i = blockIdx.x * 256 + threadIdx.x;
    float v;
    size_t o;
    if (mat < 36) {
        if (i >= WMAT_ELEMS) return;
        const float* srcs[6] = {Wq, Wk, Wv, Wo, W1, W2};
        const float* s = srcs[mat / 6] + (size_t)(mat % 6) * WMAT_ELEMS;
        int n = i >> 8, k = i & 255;
        v = s[(size_t)k * 256 + n];
        o = (size_t)mat * WMAT_ELEMS + i;
    } else {
        if (i >= WLM_ROWS * C_) return;
        int n = i >> 8, k = i & 255;
        v = (n < V_) ? Wlm[(size_t)k * V_ + n] : 0.f;
        o = WOFF_LM + i;
    }
    __nv_bfloat16 h = __float2bfloat16(v);
    hi[o] = h;
    lo[o] = __float2bfloat16(v - __bfloat162float(h));
}

// ---------------- embedding ----------------
__global__ void embed_kernel(const int* __restrict__ idx, const float* __restrict__ tok_emb,
                             const float* __restrict__ pos_emb, float* __restrict__ x,
                             __nv_bfloat16* __restrict__ xh, __nv_bfloat16* __restrict__ xl) {
    int bt = blockIdx.x, c = threadIdx.x;
    float v = tok_emb[idx[bt] * C_ + c] + pos_emb[(bt % T_) * C_ + c];
    size_t o = (size_t)bt * C_ + c;
    x[o] = v;
    __nv_bfloat16 h = __float2bfloat16(v);
    xh[o] = h;
    xl[o] = __float2bfloat16(v - __bfloat162float(h));
}

// ---------------- NEW: split GEMM, CTA 128x128, K=32 chunks, 2 CTAs/SM -----
// MODE 0: fp32 out (+bias), row stride ld, guard col<ld.
// MODE 1: relu + bf16 hi/lo out (stride 256) at column offset col0.
template <int MODE>
__global__ void __launch_bounds__(256, 2)
hmma_split(const __nv_bfloat16* __restrict__ Ah, const __nv_bfloat16* __restrict__ Al,
           const __nv_bfloat16* __restrict__ BhBase, const __nv_bfloat16* __restrict__ BlBase,
           size_t wstride, int ncolblk, float* outF, size_t ostride, int ld,
           __nv_bfloat16* __restrict__ outH, __nv_bfloat16* __restrict__ outL,
           const float* __restrict__ bias) {
    extern __shared__ char smem[];
    const uint32_t sb = smem_u32(smem);
    constexpr int STAGE = 40960;     // 4 regions x 128 rows x 80B
    const int tid = threadIdx.x, lane = tid & 31, w = tid >> 5;
    const int wm = w & 1, wn = w >> 1;
    const int mat = blockIdx.y / ncolblk, cb = blockIdx.y % ncolblk;
    const int col0 = cb * 128;
    const size_t rowblock = (size_t)blockIdx.x * 128;
    const __nv_bfloat16* Bh = BhBase + (size_t)mat * wstride + (size_t)col0 * 256;
    const __nv_bfloat16* Bl = BlBase + (size_t)mat * wstride + (size_t)col0 * 256;
    if (MODE == 0) outF += (size_t)mat * ostride;

    float acc[4][4][4];
#pragma unroll
    for (int i = 0; i < 4; i++)
#pragma unroll
        for (int j = 0; j < 4; j++)
#pragma unroll
            for (int r = 0; r < 4; r++) acc[i][j][r] = 0.f;

    auto load_stage = [&](int s, int buf) {
        const int k0 = s * 32;
        const uint32_t base = sb + buf * STAGE;
#pragma unroll
        for (int c = tid; c < 2048; c += 256) {
            int reg = c >> 9, cc = c & 511, r = cc >> 2, c4 = cc & 3;
            const __nv_bfloat16* src;
            if (reg == 0)      src = Ah + (rowblock + r) * 256 + k0 + c4 * 8;
            else if (reg == 1) src = Al + (rowblock + r) * 256 + k0 + c4 * 8;
            else if (reg == 2) src = Bh + (size_t)r * 256 + k0 + c4 * 8;
            else               src = Bl + (size_t)r * 256 + k0 + c4 * 8;
            cp_async16(base + reg * 10240 + r * 80 + c4 * 16, src);
        }
        cp_commit();
    };

    load_stage(0, 0);
    for (int s = 0; s < 8; s++) {
        if (s < 7) { load_stage(s + 1, (s + 1) & 1); cp_wait<1>(); }
        else       { cp_wait<0>(); }
        __syncthreads();
        const uint32_t base = sb + (s & 1) * STAGE;
#pragma unroll
        for (int ks = 0; ks < 2; ks++) {
            uint32_t ah[4][4], al[4][4];
#pragma unroll
            for (int i = 0; i < 4; i++) {
                int r = wm * 64 + i * 16 + (lane & 15);
                int u = 2 * ks + (lane >> 4);
                ldmatrix_x4(ah[i], base + r * 80 + u * 16);
                ldmatrix_x4(al[i], base + 10240 + r * 80 + u * 16);
            }
#pragma unroll
            for (int j2 = 0; j2 < 2; j2++) {
                int r = wn * 32 + j2 * 16 + ((lane >> 4) & 1) * 8 + (lane & 7);
                int u = 2 * ks + ((lane >> 3) & 1);
                uint32_t bh4[4], bl4[4];
                ldmatrix_x4(bh4, base + 20480 + r * 80 + u * 16);
                ldmatrix_x4(bl4, base + 30720 + r * 80 + u * 16);
#pragma unroll
                for (int i = 0; i < 4; i++) {
                    mma16816(acc[i][2 * j2],     ah[i], bh4);
                    mma16816(acc[i][2 * j2 + 1], ah[i], bh4 + 2);
                }
#pragma unroll
                for (int i = 0; i < 4; i++) {
                    mma16816(acc[i][2 * j2],     ah[i], bl4);
                    mma16816(acc[i][2 * j2 + 1], ah[i], bl4 + 2);
                }
#pragma unroll
                for (int i = 0; i < 4; i++) {
                    mma16816(acc[i][2 * j2],     al[i], bh4);
                    mma16816(acc[i][2 * j2 + 1], al[i], bh4 + 2);
                }
            }
        }
        __syncthreads();
    }

    const int g = lane >> 2, tg = lane & 3;
#pragma unroll
    for (int i = 0; i < 4; i++)
#pragma unroll
        for (int j = 0; j < 4; j++) {
            int colg = col0 + wn * 32 + j * 8 + tg * 2;
            size_t r0 = rowblock + wm * 64 + i * 16 + g;
            size_t r1 = r0 + 8;
            if (MODE == 0) {
                if (colg >= ld) continue;
                float b0 = bias ? bias[colg] : 0.f;
                float b1 = bias ? bias[colg + 1] : 0.f;
                *(float2*)(outF + r0 * ld + colg) =
                    make_float2(acc[i][j][0] + b0, acc[i][j][1] + b1);
                *(float2*)(outF + r1 * ld + colg) =
                    make_float2(acc[i][j][2] + b0, acc[i][j][3] + b1);
            } else {
                float b0 = bias[colg], b1 = bias[colg + 1];
                float v00 = fmaxf(acc[i][j][0] + b0, 0.f);
                float v01 = fmaxf(acc[i][j][1] + b1, 0.f);
                float v10 = fmaxf(acc[i][j][2] + b0, 0.f);
                float v11 = fmaxf(acc[i][j][3] + b1, 0.f);
                __nv_bfloat16 h00 = __float2bfloat16(v00), h01 = __float2bfloat16(v01);
                __nv_bfloat16 h10 = __float2bfloat16(v10), h11 = __float2bfloat16(v11);
                *(__nv_bfloat162*)(outH + r0 * C_ + colg) = __nv_bfloat162(h00, h01);
                *(__nv_bfloat162*)(outH + r1 * C_ + colg) = __nv_bfloat162(h10, h11);
                *(__nv_bfloat162*)(outL + r0 * C_ + colg) = __nv_bfloat162(
                    __float2bfloat16(v00 - __bfloat162float(h00)),
                    __float2bfloat16(v01 - __bfloat162float(h01)));
                *(__nv_bfloat162*)(outL + r1 * C_ + colg) = __nv_bfloat162(
                    __float2bfloat16(v10 - __bfloat162float(h10)),
                    __float2bfloat16(v11 - __bfloat162float(h11)));
            }
        }
}

// ---------------- fused GEMM + residual + LN (NT=256, unchanged) -----------
__global__ void __launch_bounds__(256)
hmma_ln(const __nv_bfloat16* __restrict__ Ah, const __nv_bfloat16* __restrict__ Al,
        const __nv_bfloat16* __restrict__ Bh, const __nv_bfloat16* __restrict__ Bl,
        float* outF, __nv_bfloat16* __restrict__ outH, __nv_bfloat16* __restrict__ outL,
        const float* __restrict__ bias, const float* __restrict__ res,
        const float* __restrict__ lnw, const float* __restrict__ lnb) {
    extern __shared__ char smem[];
    const uint32_t sb = smem_u32(smem);
    constexpr int NT = 256;
    constexpr int AHo = 0, ALo = 16384, BHo = 32768, BLo = 32768 + NT * 128;
    constexpr int STAGE = 32768 + 2 * NT * 128;
    constexpr int NCH = 2048 + NT * 16;
    constexpr int WN = 64, FJ = 8, FJ2 = 4;

    const int tid = threadIdx.x, lane = tid & 31, w = tid >> 5;
    const int wm = w & 1, wn = w >> 1;
    const size_t rowblock = (size_t)blockIdx.x * 128;

    float acc[4][FJ][4];
#pragma unroll
    for (int i = 0; i < 4; i++)
#pragma unroll
        for (int j = 0; j < FJ; j++)
#pragma unroll
            for (int r = 0; r < 4; r++) acc[i][j][r] = 0.f;

    auto load_stage = [&](int s, int buf) {
        const int k0 = s * 64;
        const uint32_t base = sb + buf * STAGE;
#pragma unroll
        for (int c = tid; c < NCH; c += 256) {
            if (c < 1024) {
                int r = c >> 3, h = c & 7;
                cp_async16(base + AHo + r * 128 + 16 * (h ^ (r & 7)),
                           Ah + (rowblock + r) * 256 + k0 + h * 8);
            } else if (c < 2048) {
                int cc = c - 1024;
                int r = cc >> 3, h = cc & 7;
                cp_async16(base + ALo + r * 128 + 16 * (h ^ (r & 7)),
                           Al + (rowblock + r) * 256 + k0 + h * 8);
            } else if (c < 2048 + NT * 8) {
                int cc = c - 2048;
                int r = cc >> 3, h = cc & 7;
                cp_async16(base + BHo + r * 128 + 16 * (h ^ (r & 7)),
                           Bh + (size_t)r * 256 + k0 + h * 8);
            } else {
                int cc = c - 2048 - NT * 8;
                int r = cc >> 3, h = cc & 7;
                cp_async16(base + BLo + r * 128 + 16 * (h ^ (r & 7)),
                           Bl + (size_t)r * 256 + k0 + h * 8);
            }
        }
        cp_commit();
    };

    load_stage(0, 0);
    for (int s = 0; s < 4; s++) {
        if (s < 3) { load_stage(s + 1, (s + 1) & 1); cp_wait<1>(); }
        else       { cp_wait<0>(); }
        __syncthreads();
        const uint32_t base = sb + (s & 1) * STAGE;
#pragma unroll
        for (int ks = 0; ks < 4; ks++) {
            uint32_t ah[4][4], al[4][4];
#pragma unroll
            for (int i = 0; i < 4; i++) {
                int r = wm * 64 + i * 16 + (lane & 15);
                int hh = 2 * ks + (lane >> 4);
                uint32_t off = r * 128 + 16 * (hh ^ (r & 7));
                ldmatrix_x4(ah[i], base + AHo + off);
                ldmatrix_x4(al[i], base + ALo + off);
            }
#pragma unroll
            for (int j2 = 0; j2 < FJ2; j2++) {
                int r = wn * WN + j2 * 16 + ((lane >> 4) & 1) * 8 + (lane & 7);
                int hh = 2 * ks + ((lane >> 3) & 1);
                uint32_t off = r * 128 + 16 * (hh ^ (r & 7));
                uint32_t bh4[4], bl4[4];
                ldmatrix_x4(bh4, base + BHo + off);
                ldmatrix_x4(bl4, base + BLo + off);
#pragma unroll
                for (int i = 0; i < 4; i++) {
                    mma16816(acc[i][2 * j2],     ah[i], bh4);
                    mma16816(acc[i][2 * j2 + 1], ah[i], bh4 + 2);
                }
#pragma unroll
                for (int i = 0; i < 4; i++) {
                    mma16816(acc[i][2 * j2],     ah[i], bl4);
                    mma16816(acc[i][2 * j2 + 1], ah[i], bl4 + 2);
                }
#pragma unroll
                for (int i = 0; i < 4; i++) {
                    mma16816(acc[i][2 * j2],     al[i], bh4);
                    mma16816(acc[i][2 * j2 + 1], al[i], bh4 + 2);
                }
            }
        }
        __syncthreads();
    }

    const int g = lane >> 2, tg = lane & 3;
    float* rs = (float*)smem;
    float* rq = rs + 512;
    float vsum[4][2], vsq[4][2];
#pragma unroll
    for (int i = 0; i < 4; i++) { vsum[i][0] = vsum[i][1] = vsq[i][0] = vsq[i][1] = 0.f; }
#pragma unroll
    for (int i = 0; i < 4; i++)
#pragma unroll
        for (int j = 0; j < FJ; j++) {
            int col = wn * WN + j * 8 + tg * 2;
            size_t r0 = rowblock + wm * 64 + i * 16 + g;
            size_t r1 = r0 + 8;
            float b0 = bias[col], b1 = bias[col + 1];
            float2 q0 = *(const float2*)(res + r0 * NT + col);
            float2 q1 = *(const float2*)(res + r1 * NT + col);
            float v00 = acc[i][j][0] + b0 + q0.x;
            float v01 = acc[i][j][1] + b1 + q0.y;
            float v10 = acc[i][j][2] + b0 + q1.x;
            float v11 = acc[i][j][3] + b1 + q1.y;
            acc[i][j][0] = v00; acc[i][j][1] = v01;
            acc[i][j][2] = v10; acc[i][j][3] = v11;
            vsum[i][0] += v00 + v01;  vsq[i][0] += v00 * v00 + v01 * v01;
            vsum[i][1] += v10 + v11;  vsq[i][1] += v10 * v10 + v11 * v11;
        }
#pragma unroll
    for (int i = 0; i < 4; i++)
#pragma unroll
        for (int hf = 0; hf < 2; hf++) {
            float s = vsum[i][hf], q = vsq[i][hf];
            s += __shfl_xor_sync(0xffffffffu, s, 1);
            s += __shfl_xor_sync(0xffffffffu, s, 2);
            q += __shfl_xor_sync(0xffffffffu, q, 1);
            q += __shfl_xor_sync(0xffffffffu, q, 2);
            if (tg == 0) {
                int lr = wm * 64 + i * 16 + hf * 8 + g;
                rs[lr * 4 + wn] = s;
                rq[lr * 4 + wn] = q;
            }
        }
    __syncthreads();
    float mean[4][2], rstd[4][2];
#pragma unroll
    for (int i = 0; i < 4; i++)
#pragma unroll
        for (int hf = 0; hf < 2; hf++) {
            int lr = wm * 64 + i * 16 + hf * 8 + g;
            float S = rs[lr * 4] + rs[lr * 4 + 1] + rs[lr * 4 + 2] + rs[lr * 4 + 3];
            float Q = rq[lr * 4] + rq[lr * 4 + 1] + rq[lr * 4 + 2] + rq[lr * 4 + 3];
            float mn = S * (1.f / NT);
            mean[i][hf] = mn;
            rstd[i][hf] = rsqrtf(Q * (1.f / NT) - mn * mn + EPS_);
        }
#pragma unroll
    for (int i = 0; i < 4; i++)
#pragma unroll
        for (int j = 0; j < FJ; j++) {
            int col = wn * WN + j * 8 + tg * 2;
            size_t r0 = rowblock + wm * 64 + i * 16 + g;
            size_t r1 = r0 + 8;
            float w0 = lnw[col], w1 = lnw[col + 1];
            float c0 = lnb[col], c1 = lnb[col + 1];
            float v00 = (acc[i][j][0] - mean[i][0]) * rstd[i][0] * w0 + c0;
            float v01 = (acc[i][j][1] - mean[i][0]) * rstd[i][0] * w1 + c1;
            float v10 = (acc[i][j][2] - mean[i][1]) * rstd[i][1] * w0 + c0;
            float v11 = (acc[i][j][3] - mean[i][1]) * rstd[i][1] * w1 + c1;
            *(float2*)(outF + r0 * NT + col) = make_float2(v00, v01);
            *(float2*)(outF + r1 * NT + col) = make_float2(v10, v11);
            __nv_bfloat16 h00 = __float2bfloat16(v00), h01 = __float2bfloat16(v01);
            __nv_bfloat16 h10 = __float2bfloat16(v10), h11 = __float2bfloat16(v11);
            *(__nv_bfloat162*)(outH + r0 * NT + col) = __nv_bfloat162(h00, h01);
            *(__nv_bfloat162*)(outH + r1 * NT + col) = __nv_bfloat162(h10, h11);
            *(__nv_bfloat162*)(outL + r0 * NT + col) = __nv_bfloat162(
                __float2bfloat16(v00 - __bfloat162float(h00)),
                __float2bfloat16(v01 - __bfloat162float(h01)));
            *(__nv_bfloat162*)(outL + r1 * NT + col) = __nv_bfloat162(
                __float2bfloat16(v10 - __bfloat162float(h10)),
                __float2bfloat16(v11 - __bfloat162float(h11)));
        }
}

// ---------------- flash attention (round-6) ----------------
#define AQH 0
#define AQL 10240
#define AKH 20480
#define AKL 40960
#define AVH 61440
#define AVL 78336
#define ATTN_SMEM 95232

__global__ void __launch_bounds__(256, 2)
flash_attn(const float* __restrict__ qkv,
           __nv_bfloat16* __restrict__ outH, __nv_bfloat16* __restrict__ outL) {
    extern __shared__ char smem[];
    const uint32_t sb = smem_u32(smem);
    const int tid = threadIdx.x, lane = tid & 31;
    const int wrow = (tid >> 5) * 16;
    const int g = lane >> 2, tg = lane & 3;
    const int qb = blockIdx.x, bh = blockIdx.y;
    const int b = bh >> 3, h = bh & 7;

    const float* qp = qkv + ((size_t)(b * T_ + qb * 128)) * C_ + h * HS_;
    const float* kp = qkv + (size_t)BT_ * C_ + (size_t)(b * T_) * C_ + h * HS_;
    const float* vp = kp + (size_t)BT_ * C_;

#pragma unroll
    for (int it = 0; it < 4; it++) {
        int i = tid + it * 256;
        int r = i >> 3, c4 = i & 7;
        float4 f = *(const float4*)(qp + (size_t)r * C_ + c4 * 4);
        f.x *= 0.0625f; f.y *= 0.0625f; f.z *= 0.0625f; f.w *= 0.0625f;
        uint32_t o = r * 80 + c4 * 8;
        uint32_t h01 = packbf2(f.x, f.y), h23 = packbf2(f.z, f.w);
        *(uint32_t*)(smem + AQH + o)     = h01;
        *(uint32_t*)(smem + AQH + o + 4) = h23;
        __nv_bfloat162* p01 = (__nv_bfloat162*)&h01;
        __nv_bfloat162* p23 = (__nv_bfloat162*)&h23;
        *(uint32_t*)(smem + AQL + o) = packbf2(f.x - __bfloat162float(p01->x),
                                               f.y - __bfloat162float(p01->y));
        *(uint32_t*)(smem + AQL + o + 4) = packbf2(f.z - __bfloat162float(p23->x),
                                                   f.w - __bfloat162float(p23->y));
    }
#pragma unroll
    for (int it = 0; it < 8; it++) {
        int i = tid + it * 256;
        int r = i >> 3, c4 = i & 7;
        float4 f = *(const float4*)(kp + (size_t)r * C_ + c4 * 4);
        uint32_t o = r * 80 + c4 * 8;
        uint32_t h01 = packbf2(f.x, f.y), h23 = packbf2(f.z, f.w);
        *(uint32_t*)(smem + AKH + o)     = h01;
        *(uint32_t*)(smem + AKH + o + 4) = h23;
        __nv_bfloat162* p01 = (__nv_bfloat162*)&h01;
        __nv_bfloat162* p23 = (__nv_bfloat162*)&h23;
        *(uint32_t*)(smem + AKL + o) = packbf2(f.x - __bfloat162float(p01->x),
                                               f.y - __bfloat162float(p01->y));
        *(uint32_t*)(smem + AKL + o + 4) = packbf2(f.z - __bfloat162float(p23->x),
                                                   f.w - __bfloat162float(p23->y));
    }
#pragma unroll
    for (int it = 0; it < 8; it++) {
        int i = tid + it * 256;
        int r = i >> 3, c4 = i & 7;
        float4 f = *(const float4*)(vp + (size_t)r * C_ + c4 * 4);
        float vals[4] = {f.x, f.y, f.z, f.w};
#pragma unroll
        for (int m = 0; m < 4; m++) {
            int d = c4 * 4 + m;
            __nv_bfloat16 hi = __float2bfloat16(vals[m]);
            *(__nv_bfloat16*)(smem + AVH + d * 528 + r * 2) = hi;
            *(__nv_bfloat16*)(smem + AVL + d * 528 + r * 2) =
                __float2bfloat16(vals[m] - __bfloat162float(hi));
        }
    }
    __syncthreads();

    uint32_t qf_h[2][4], qf_l[2][4];
#pragma unroll
    for (int ks = 0; ks < 2; ks++) {
        int r = wrow + (lane & 15);
        int hh = 2 * ks + (lane >> 4);
        ldmatrix_x4(qf_h[ks], sb + AQH + r * 80 + hh * 16);
        ldmatrix_x4(qf_l[ks], sb + AQL + r * 80 + hh * 16);
    }

    float m0 = -INFINITY, m1 = -INFINITY, l0 = 0.f, l1 = 0.f;
    float oacc[4][4];
#pragma unroll
    for (int nd = 0; nd < 4; nd++)
#pragma unroll
        for (int r = 0; r < 4; r++) oacc[nd][r] = 0.f;

    const int nch = (qb == 0) ? 2 : 4;
    const int qrow = qb * 128 + wrow + g;

    for (int ch = 0; ch < nch; ch++) {
        const int kbase = ch * 64;
        float sacc[8][4];
#pragma unroll
        for (int j = 0; j < 8; j++)
#pragma unroll
            for (int r = 0; r < 4; r++) sacc[j][r] = 0.f;
#pragma unroll
        for (int ks = 0; ks < 2; ks++) {
            uint32_t bh_[8][2], bl_[8][2];
#pragma unroll
            for (int j2 = 0; j2 < 4; j2++) {
                int r = kbase + j2 * 16 + ((lane >> 4) & 1) * 8 + (lane & 7);
                int hh = 2 * ks + ((lane >> 3) & 1);
                uint32_t t4[4];
                ldmatrix_x4(t4, sb + AKH + r * 80 + hh * 16);
                bh_[2 * j2][0] = t4[0]; bh_[2 * j2][1] = t4[1];
                bh_[2 * j2 + 1][0] = t4[2]; bh_[2 * j2 + 1][1] = t4[3];
                ldmatrix_x4(t4, sb + AKL + r * 80 + hh * 16);
                bl_[2 * j2][0] = t4[0]; bl_[2 * j2][1] = t4[1];
                bl_[2 * j2 + 1][0] = t4[2]; bl_[2 * j2 + 1][1] = t4[3];
            }
#pragma unroll
            for (int j = 0; j < 8; j++) mma16816(sacc[j], qf_h[ks], bh_[j]);
#pragma unroll
            for (int j = 0; j < 8; j++) mma16816(sacc[j], qf_h[ks], bl_[j]);
#pragma unroll
            for (int j = 0; j < 8; j++) mma16816(sacc[j], qf_l[ks], bh_[j]);
        }
        if (kbase + 63 > qb * 128 + wrow) {
#pragma unroll
            for (int j = 0; j < 8; j++) {
                int key = kbase + j * 8 + tg * 2;
                if (key     > qrow)     sacc[j][0] = -1e30f;
                if (key + 1 > qrow)     sacc[j][1] = -1e30f;
                if (key     > qrow + 8) sacc[j][2] = -1e30f;
                if (key + 1 > qrow + 8) sacc[j][3] = -1e30f;
            }
        }
        uint32_t ph[8][2], pl[8][2];
        {
            float mx0 = -1e30f, mx1 = -1e30f;
#pragma unroll
            for (int j = 0; j < 8; j++) {
                mx0 = fmaxf(mx0, fmaxf(sacc[j][0], sacc[j][1]));
                mx1 = fmaxf(mx1, fmaxf(sacc[j][2], sacc[j][3]));
            }
            mx0 = fmaxf(mx0, __shfl_xor_sync(0xffffffffu, mx0, 1));
            mx0 = fmaxf(mx0, __shfl_xor_sync(0xffffffffu, mx0, 2));
            mx1 = fmaxf(mx1, __shfl_xor_sync(0xffffffffu, mx1, 1));
            mx1 = fmaxf(mx1, __shfl_xor_sync(0xffffffffu, mx1, 2));
            float mn0 = fmaxf(m0, mx0), mn1 = fmaxf(m1, mx1);
            float cr0 = __expf(m0 - mn0), cr1 = __expf(m1 - mn1);
            float rs0 = 0.f, rs1 = 0.f;
#pragma unroll
            for (int j = 0; j < 8; j++) {
                float p0 = __expf(sacc[j][0] - mn0);
                float p1 = __expf(sacc[j][1] - mn0);
                float p2 = __expf(sacc[j][2] - mn1);
                float p3 = __expf(sacc[j][3] - mn1);
                rs0 += p0 + p1; rs1 += p2 + p3;
                ph[j][0] = packbf2(p0, p1);
                ph[j][1] = packbf2(p2, p3);
                __nv_bfloat162* t0 = (__nv_bfloat162*)&ph[j][0];
                __nv_bfloat162* t1 = (__nv_bfloat162*)&ph[j][1];
                pl[j][0] = packbf2(p0 - __bfloat162float(t0->x), p1 - __bfloat162float(t0->y));
                pl[j][1] = packbf2(p2 - __bfloat162float(t1->x), p3 - __bfloat162float(t1->y));
            }
            rs0 += __shfl_xor_sync(0xffffffffu, rs0, 1);
            rs0 += __shfl_xor_sync(0xffffffffu, rs0, 2);
            rs1 += __shfl_xor_sync(0xffffffffu, rs1, 1);
            rs1 += __shfl_xor_sync(0xffffffffu, rs1, 2);
            l0 = l0 * cr0 + rs0;  l1 = l1 * cr1 + rs1;
            m0 = mn0;  m1 = mn1;
#pragma unroll
            for (int nd = 0; nd < 4; nd++) {
                oacc[nd][0] *= cr0; oacc[nd][1] *= cr0;
                oacc[nd][2] *= cr1; oacc[nd][3] *= cr1;
            }
        }
#pragma unroll
        for (int kk = 0; kk < 4; kk++) {
            uint32_t pa_h[4] = {ph[2 * kk][0], ph[2 * kk][1],
                                ph[2 * kk + 1][0], ph[2 * kk + 1][1]};
            uint32_t pa_l[4] = {pl[2 * kk][0], pl[2 * kk][1],
                                pl[2 * kk + 1][0], pl[2 * kk + 1][1]};
            uint32_t vh[4][2], vl[4][2];
#pragma unroll
            for (int nd2 = 0; nd2 < 2; nd2++) {
                int r = nd2 * 16 + ((lane >> 4) & 1) * 8 + (lane & 7);
                int hh = (kbase >> 3) + 2 * kk + ((lane >> 3) & 1);
                uint32_t t4[4];
                ldmatrix_x4(t4, sb + AVH + r * 528 + hh * 16);
                vh[2 * nd2][0] = t4[0]; vh[2 * nd2][1] = t4[1];
                vh[2 * nd2 + 1][0] = t4[2]; vh[2 * nd2 + 1][1] = t4[3];
                ldmatrix_x4(t4, sb + AVL + r * 528 + hh * 16);
                vl[2 * nd2][0] = t4[0]; vl[2 * nd2][1] = t4[1];
                vl[2 * nd2 + 1][0] = t4[2]; vl[2 * nd2 + 1][1] = t4[3];
            }
#pragma unroll
            for (int nd = 0; nd < 4; nd++) mma16816(oacc[nd], pa_h, vh[nd]);
#pragma unroll
            for (int nd = 0; nd < 4; nd++) mma16816(oacc[nd], pa_h, vl[nd]);
#pragma unroll
            for (int nd = 0; nd < 4; nd++) mma16816(oacc[nd], pa_l, vh[nd]);
        }
    }

    float inv0 = 1.f / l0, inv1 = 1.f / l1;
    size_t r0 = (size_t)(b * T_) + qb * 128 + wrow + g, r1 = r0 + 8;
#pragma unroll
    for (int nd = 0; nd < 4; nd++) {
        int col = h * 32 + nd * 8 + tg * 2;
        float v00 = oacc[nd][0] * inv0, v01 = oacc[nd][1] * inv0;
        float v10 = oacc[nd][2] * inv1, v11 = oacc[nd][3] * inv1;
        __nv_bfloat16 h00 = __float2bfloat16(v00), h01 = __float2bfloat16(v01);
        __nv_bfloat16 h10 = __float2bfloat16(v10), h11 = __float2bfloat16(v11);
        *(__nv_bfloat162*)(outH + r0 * C_ + col) = __nv_bfloat162(h00, h01);
        *(__nv_bfloat162*)(outH + r1 * C_ + col) = __nv_bfloat162(h10, h11);
        *(__nv_bfloat162*)(outL + r0 * C_ + col) = __nv_bfloat162(
            __float2bfloat16(v00 - __bfloat162float(h00)),
            __float2bfloat16(v01 - __bfloat162float(h01)));
        *(__nv_bfloat162*)(outL + r1 * C_ + col) = __nv_bfloat162(
            __float2bfloat16(v10 - __bfloat162float(h10)),
            __float2bfloat16(v11 - __bfloat162float(h11)));
    }
}

// ---------------- final layernorm ----------------
__global__ void add_ln_kernel(const float* __restrict__ x, const float* __restrict__ w,
                              const float* __restrict__ b,
                              __nv_bfloat16* __restrict__ outH, __nv_bfloat16* __restrict__ outL) {
    const int row = blockIdx.x, c = threadIdx.x;
    float v = x[(size_t)row * C_ + c];
    float s = v, s2 = v * v;
    __shared__ float sh1[8], sh2[8];
#pragma unroll
    for (int o = 16; o; o >>= 1) {
        s  += __shfl_xor_sync(0xffffffffu, s, o);
        s2 += __shfl_xor_sync(0xffffffffu, s2, o);
    }
    if ((c & 31) == 0) { sh1[c >> 5] = s; sh2[c >> 5] = s2; }
    __syncthreads();
    float S = 0.f, Q = 0.f;
#pragma unroll
    for (int i = 0; i < 8; i++) { S += sh1[i]; Q += sh2[i]; }
    float mean = S * (1.f / C_);
    float var  = Q * (1.f / C_) - mean * mean;
    float r = (v - mean) * rsqrtf(var + EPS_) * w[c] + b[c];
    size_t o = (size_t)row * C_ + c;
    __nv_bfloat16 hi = __float2bfloat16(r);
    outH[o] = hi;
    outL[o] = __float2bfloat16(r - __bfloat162float(hi));
}

// ---------------- NLL + loss ----------------
__global__ void nll_kernel(const float* __restrict__ logits, const int* __restrict__ tgt,
                           float* __restrict__ nll) {
    int warp = (blockIdx.x * blockDim.x + threadIdx.x) >> 5;
    int lane = threadIdx.x & 31;
    if (warp >= BT_) return;
    const float* l = logits + (size_t)warp * V_;
    float mx = -INFINITY;
    for (int c = lane; c < V_; c += 32) mx = fmaxf(mx, l[c]);
#pragma unroll
    for (int o = 16; o; o >>= 1) mx = fmaxf(mx, __shfl_xor_sync(0xffffffffu, mx, o));
    float s = 0.f;
    for (int c = lane; c < V_; c += 32) s += __expf(l[c] - mx);
#pragma unroll
    for (int o = 16; o; o >>= 1) s += __shfl_xor_sync(0xffffffffu, s, o);
    if (lane == 0) nll[warp] = -(l[tgt[warp]] - mx - __logf(s));
}
__global__ void reduce_loss_kernel(const float* __restrict__ nll, float* __restrict__ out) {
    __shared__ float sh[256];
    float s = 0.f;
    for (int i = threadIdx.x; i < BT_; i += 256) s += nll[i];
    sh[threadIdx.x] = s;
    __syncthreads();
    for (int st = 128; st; st >>= 1) {
        if (threadIdx.x < st) sh[threadIdx.x] += sh[threadIdx.x + st];
        __syncthreads();
    }
    if (threadIdx.x == 0) *out = sh[0] * (1.f / BT_);
}

// ---------------- host driver ----------------
extern "C" void kernel_launch(void* const* d_in, const int* in_sizes, int n_in,
                              void* d_out, int out_size) {
    const int*   idx     = (const int*)  d_in[0];
    const int*   target  = (const int*)  d_in[1];
    const float* tok_emb = (const float*)d_in[2];
    const float* pos_emb = (const float*)d_in[3];
    const float* Wq      = (const float*)d_in[4];
    const float* Wk      = (const float*)d_in[5];
    const float* Wv      = (const float*)d_in[6];
    const float* Wo      = (const float*)d_in[7];
    const float* bo      = (const float*)d_in[8];
    const float* W1      = (const float*)d_in[9];
    const float* b1      = (const float*)d_in[10];
    const float* W2      = (const float*)d_in[11];
    const float* b2_     = (const float*)d_in[12];
    const float* ln1_w   = (const float*)d_in[13];
    const float* ln1_b   = (const float*)d_in[14];
    const float* ln2_w   = (const float*)d_in[15];
    const float* ln2_b   = (const float*)d_in[16];
    const float* lnf_w   = (const float*)d_in[17];
    const float* lnf_b   = (const float*)d_in[18];
    const float* Wlm     = (const float*)d_in[19];
    const float* blm     = (const float*)d_in[20];

    float *px, *pqkv, *pnll;
    __nv_bfloat16 *pxh, *pxl, *pah, *pal, *phh, *phl, *pwh, *pwl;
    cudaGetSymbolAddress((void**)&px,   g_x);
    cudaGetSymbolAddress((void**)&pqkv, g_qkv);
    cudaGetSymbolAddress((void**)&pnll, g_nll);
    cudaGetSymbolAddress((void**)&pxh,  g_xh);
    cudaGetSymbolAddress((void**)&pxl,  g_xl);
    cudaGetSymbolAddress((void**)&pah,  g_ah);
    cudaGetSymbolAddress((void**)&pal,  g_al);
    cudaGetSymbolAddress((void**)&phh,  g_hh);
    cudaGetSymbolAddress((void**)&phl,  g_hl);
    cudaGetSymbolAddress((void**)&pwh,  g_wh);
    cudaGetSymbolAddress((void**)&pwl,  g_wl);

    cudaFuncSetAttribute(flash_attn, cudaFuncAttributeMaxDynamicSharedMemorySize, ATTN_SMEM);
    const int smemLN = 2 * (32768 + 2 * 256 * 128);   // 196608
    const int smemS  = 2 * 40960;                     // 81920
    cudaFuncSetAttribute(hmma_ln, cudaFuncAttributeMaxDynamicSharedMemorySize, smemLN);
    cudaFuncSetAttribute(hmma_split<0>, cudaFuncAttributeMaxDynamicSharedMemorySize, smemS);
    cudaFuncSetAttribute(hmma_split<1>, cudaFuncAttributeMaxDynamicSharedMemorySize, smemS);

    convw_all<<<dim3(256, 37), 256>>>(Wq, Wk, Wv, Wo, W1, W2, Wlm, pwh, pwl);
    embed_kernel<<<BT_, C_>>>(idx, tok_emb, pos_emb, px, pxh, pxl);

    const size_t QKV_OSTRIDE = (size_t)BT_ * C_;
    const size_t QKV_WSTRIDE = (size_t)6 * WMAT_ELEMS;

    for (int l = 0; l < L_; l++) {
        // QKV: 768 CTAs (3 mats x 2 col blocks), 2 CTAs/SM
        hmma_split<0><<<dim3(128, 6), 256, smemS>>>(pxh, pxl,
            pwh + WOFF(0, l), pwl + WOFF(0, l), QKV_WSTRIDE, 2,
            pqkv, QKV_OSTRIDE, C_, nullptr, nullptr, nullptr);
        flash_attn<<<dim3(2, B_ * H_), 256, ATTN_SMEM>>>(pqkv, pah, pal);
        hmma_ln<<<128, 256, smemLN>>>(pah, pal,
            pwh + WOFF(3, l), pwl + WOFF(3, l),
            px, pxh, pxl, bo + l * C_, px, ln1_w + l * C_, ln1_b + l * C_);
        // W1: 256 CTAs (2 col blocks), relu, bf16 hi/lo out
        hmma_split<1><<<dim3(128, 2), 256, smemS>>>(pxh, pxl,
            pwh + WOFF(4, l), pwl + WOFF(4, l), 0, 2,
            nullptr, 0, C_, phh, phl, b1 + l * C_);
        hmma_ln<<<128, 256, smemLN>>>(phh, phl,
            pwh + WOFF(5, l), pwl + WOFF(5, l),
            px, pxh, pxl, b2_ + l * C_, px, ln2_w + l * C_, ln2_b + l * C_);
    }
    add_ln_kernel<<<BT_, C_>>>(px, lnf_w, lnf_b, pxh, pxl);

    float* logits = (out_size >= BT_ * V_) ? (float*)d_out : pqkv;
    hmma_split<0><<<dim3(128, 1), 256, smemS>>>(pxh, pxl,
        pwh + WOFF_LM, pwl + WOFF_LM, 0, 1,
        logits, 0, V_, nullptr, nullptr, blm);

    nll_kernel<<<(BT_ * 32 + 255) / 256, 256>>>(logits, target, pnll);

    float* loss_dst = nullptr;
    if (out_size == 1)            loss_dst = (float*)d_out;
    else if (out_size > BT_ * V_) loss_dst = (float*)d_out + BT_ * V_;
    if (loss_dst) reduce_loss_kernel<<<1, 256>>>(pnll, loss_dst);
}

// round 14
// speedup vs baseline: 1.0772x; 1.0772x over previous
#include <cuda_runtime.h>
#include <cuda_bf16.h>
#include <cstdint>
#include <math.h>

#define B_  64
#define T_  256
#define C_  256
#define H_  8
#define HS_ 32
#define L_  6
#define V_  96
#define BT_ (B_ * T_)
#define EPS_ 1e-5f

__device__ __align__(16) float g_x  [BT_ * C_];
__device__ __align__(16) float g_qkv[3 * BT_ * C_];
__device__ __align__(16) float g_nll[BT_];

__device__ __align__(16) __nv_bfloat16 g_xh [BT_ * C_];
__device__ __align__(16) __nv_bfloat16 g_xl [BT_ * C_];
__device__ __align__(16) __nv_bfloat16 g_ah [BT_ * C_];
__device__ __align__(16) __nv_bfloat16 g_al [BT_ * C_];
__device__ __align__(16) __nv_bfloat16 g_hh [BT_ * C_];
__device__ __align__(16) __nv_bfloat16 g_hl [BT_ * C_];

#define WMAT_ELEMS (C_ * C_)
#define WLM_ROWS   128
#define W_TOTAL    (36 * WMAT_ELEMS + WLM_ROWS * C_)
__device__ __align__(16) __nv_bfloat16 g_wh[W_TOTAL];
__device__ __align__(16) __nv_bfloat16 g_wl[W_TOTAL];
#define WOFF(t, l) ((size_t)((t) * 6 + (l)) * WMAT_ELEMS)
#define WOFF_LM    ((size_t)36 * WMAT_ELEMS)

// ---------------- helpers ----------------
__device__ __forceinline__ uint32_t smem_u32(const void* p) {
    uint32_t a;
    asm("{ .reg .u64 t; cvta.to.shared.u64 t, %1; cvt.u32.u64 %0, t; }" : "=r"(a) : "l"(p));
    return a;
}
__device__ __forceinline__ void cp_async16(uint32_t dst, const void* src) {
    asm volatile("cp.async.cg.shared.global [%0], [%1], 16;" :: "r"(dst), "l"(src) : "memory");
}
__device__ __forceinline__ void cp_commit() { asm volatile("cp.async.commit_group;" ::: "memory"); }
template <int N>
__device__ __forceinline__ void cp_wait() {
    asm volatile("cp.async.wait_group %0;" :: "n"(N) : "memory");
}
__device__ __forceinline__ void ldmatrix_x4(uint32_t* r, uint32_t addr) {
    asm volatile("ldmatrix.sync.aligned.m8n8.x4.shared.b16 {%0,%1,%2,%3}, [%4];"
                 : "=r"(r[0]), "=r"(r[1]), "=r"(r[2]), "=r"(r[3]) : "r"(addr));
}
__device__ __forceinline__ void mma16816(float* c, const uint32_t* a, const uint32_t* b) {
    asm volatile("mma.sync.aligned.m16n8k16.row.col.f32.bf16.bf16.f32 "
                 "{%0,%1,%2,%3}, {%4,%5,%6,%7}, {%8,%9}, {%0,%1,%2,%3};"
                 : "+f"(c[0]), "+f"(c[1]), "+f"(c[2]), "+f"(c[3])
                 : "r"(a[0]), "r"(a[1]), "r"(a[2]), "r"(a[3]), "r"(b[0]), "r"(b[1]));
}
__device__ __forceinline__ uint32_t packbf2(float a, float b) {
    __nv_bfloat162 t(__float2bfloat16(a), __float2bfloat16(b));
    return *(uint32_t*)&t;
}

// ---------------- weight transpose + hi/lo ----------------
__global__ void convw_all(const float* __restrict__ Wq, const float* __restrict__ Wk,
                          const float* __restrict__ Wv, const float* __restrict__ Wo,
                          const float* __restrict__ W1, const float* __restrict__ W2,
                          const float* __restrict__ Wlm,
                          __nv_bfloat16* __restrict__ hi, __nv_bfloat16* __restrict__ lo) {
    const int mat = blockIdx.y;
    const int i = blockIdx.x * 256 + threadIdx.x;
    float v;
    size_t o;
    if (mat < 36) {
        if (i >= WMAT_ELEMS) return;
        const float* srcs[6] = {Wq, Wk, Wv, Wo, W1, W2};
        const float* s = srcs[mat / 6] + (size_t)(mat % 6) * WMAT_ELEMS;
        int n = i >> 8, k = i & 255;
        v = s[(size_t)k * 256 + n];
        o = (size_t)mat * WMAT_ELEMS + i;
    } else {
        if (i >= WLM_ROWS * C_) return;
        int n = i >> 8, k = i & 255;
        v = (n < V_) ? Wlm[(size_t)k * V_ + n] : 0.f;
        o = WOFF_LM + i;
    }
    __nv_bfloat16 h = __float2bfloat16(v);
    hi[o] = h;
    lo[o] = __float2bfloat16(v - __bfloat162float(h));
}

// ---------------- embedding ----------------
__global__ void embed_kernel(const int* __restrict__ idx, const float* __restrict__ tok_emb,
                             const float* __restrict__ pos_emb, float* __restrict__ x,
                             __nv_bfloat16* __restrict__ xh, __nv_bfloat16* __restrict__ xl) {
    int bt = blockIdx.x, c = threadIdx.x;
    float v = tok_emb[idx[bt] * C_ + c] + pos_emb[(bt % T_) * C_ + c];
    size_t o = (size_t)bt * C_ + c;
    x[o] = v;
    __nv_bfloat16 h = __float2bfloat16(v);
    xh[o] = h;
    xl[o] = __float2bfloat16(v - __bfloat162float(h));
}

// ---------------- HMMA GEMM (round-6 core) ----------------
template <int NT, int MODE>
__global__ void __launch_bounds__(256)
hmma_gemm3(const __nv_bfloat16* __restrict__ Ah, const __nv_bfloat16* __restrict__ Al,
           const __nv_bfloat16* __restrict__ BhBase, const __nv_bfloat16* __restrict__ BlBase,
           size_t wstride, float* outF, size_t ostride,
           __nv_bfloat16* __restrict__ outH, __nv_bfloat16* __restrict__ outL,
           const float* __restrict__ bias, const float* __restrict__ res,
           const float* __restrict__ lnw, const float* __restrict__ lnb, int Nout) {
    extern __shared__ char smem[];
    const uint32_t sb = smem_u32(smem);
    constexpr int AHo = 0, ALo = 16384, BHo = 32768, BLo = 32768 + NT * 128;
    constexpr int STAGE = 32768 + 2 * NT * 128;
    constexpr int NCH   = 2048 + NT * 16;
    constexpr int WN  = NT / 4;
    constexpr int FJ  = WN / 8;
    constexpr int FJ2 = WN / 16;

    const int tid  = threadIdx.x;
    const int lane = tid & 31;
    const int w    = tid >> 5;
    const int wm   = w & 1;
    const int wn   = w >> 1;

    const size_t rowblock = (size_t)blockIdx.x * 128;
    const __nv_bfloat16* Bh = BhBase + blockIdx.y * wstride;
    const __nv_bfloat16* Bl = BlBase + blockIdx.y * wstride;
    if (MODE == 0) outF += blockIdx.y * ostride;

    float acc[4][FJ][4];
#pragma unroll
    for (int i = 0; i < 4; i++)
#pragma unroll
        for (int j = 0; j < FJ; j++)
#pragma unroll
            for (int r = 0; r < 4; r++) acc[i][j][r] = 0.f;

    auto load_stage = [&](int s, int buf) {
        const int k0 = s * 64;
        const uint32_t base = sb + buf * STAGE;
#pragma unroll
        for (int c = tid; c < NCH; c += 256) {
            if (c < 1024) {
                int r = c >> 3, h = c & 7;
                cp_async16(base + AHo + r * 128 + 16 * (h ^ (r & 7)),
                           Ah + (rowblock + r) * 256 + k0 + h * 8);
            } else if (c < 2048) {
                int cc = c - 1024;
                int r = cc >> 3, h = cc & 7;
                cp_async16(base + ALo + r * 128 + 16 * (h ^ (r & 7)),
                           Al + (rowblock + r) * 256 + k0 + h * 8);
            } else if (c < 2048 + NT * 8) {
                int cc = c - 2048;
                int r = cc >> 3, h = cc & 7;
                cp_async16(base + BHo + r * 128 + 16 * (h ^ (r & 7)),
                           Bh + (size_t)r * 256 + k0 + h * 8);
            } else {
                int cc = c - 2048 - NT * 8;
                int r = cc >> 3, h = cc & 7;
                cp_async16(base + BLo + r * 128 + 16 * (h ^ (r & 7)),
                           Bl + (size_t)r * 256 + k0 + h * 8);
            }
        }
        cp_commit();
    };

    load_stage(0, 0);
    for (int s = 0; s < 4; s++) {
        if (s < 3) { load_stage(s + 1, (s + 1) & 1); cp_wait<1>(); }
        else       { cp_wait<0>(); }
        __syncthreads();
        const uint32_t base = sb + (s & 1) * STAGE;
#pragma unroll
        for (int ks = 0; ks < 4; ks++) {
            uint32_t ah[4][4], al[4][4];
#pragma unroll
            for (int i = 0; i < 4; i++) {
                int r = wm * 64 + i * 16 + (lane & 15);
                int hh = 2 * ks + (lane >> 4);
                uint32_t off = r * 128 + 16 * (hh ^ (r & 7));
                ldmatrix_x4(ah[i], base + AHo + off);
                ldmatrix_x4(al[i], base + ALo + off);
            }
#pragma unroll
            for (int j2 = 0; j2 < FJ2; j2++) {
                int r = wn * WN + j2 * 16 + ((lane >> 4) & 1) * 8 + (lane & 7);
                int hh = 2 * ks + ((lane >> 3) & 1);
                uint32_t off = r * 128 + 16 * (hh ^ (r & 7));
                uint32_t bh4[4], bl4[4];
                ldmatrix_x4(bh4, base + BHo + off);
                ldmatrix_x4(bl4, base + BLo + off);
#pragma unroll
                for (int i = 0; i < 4; i++) {
                    mma16816(acc[i][2 * j2],     ah[i], bh4);
                    mma16816(acc[i][2 * j2 + 1], ah[i], bh4 + 2);
                    mma16816(acc[i][2 * j2],     ah[i], bl4);
                    mma16816(acc[i][2 * j2 + 1], ah[i], bl4 + 2);
                    mma16816(acc[i][2 * j2],     al[i], bh4);
                    mma16816(acc[i][2 * j2 + 1], al[i], bh4 + 2);
                }
            }
        }
        __syncthreads();
    }

    const int g  = lane >> 2;
    const int tg = lane & 3;

    if (MODE == 0) {
#pragma unroll
        for (int i = 0; i < 4; i++)
#pragma unroll
            for (int j = 0; j < FJ; j++) {
                int col = wn * WN + j * 8 + tg * 2;
                if (col >= Nout) continue;
                size_t r0 = rowblock + wm * 64 + i * 16 + g;
                size_t r1 = r0 + 8;
                float b0 = bias ? bias[col] : 0.f;
                float b1 = bias ? bias[col + 1] : 0.f;
                *(float2*)(outF + r0 * Nout + col) =
                    make_float2(acc[i][j][0] + b0, acc[i][j][1] + b1);
                *(float2*)(outF + r1 * Nout + col) =
                    make_float2(acc[i][j][2] + b0, acc[i][j][3] + b1);
            }
    } else if (MODE == 1) {
#pragma unroll
        for (int i = 0; i < 4; i++)
#pragma unroll
            for (int j = 0; j < FJ; j++) {
                int col = wn * WN + j * 8 + tg * 2;
                size_t r0 = rowblock + wm * 64 + i * 16 + g;
                size_t r1 = r0 + 8;
                float b0 = bias[col], b1 = bias[col + 1];
                float v00 = fmaxf(acc[i][j][0] + b0, 0.f);
                float v01 = fmaxf(acc[i][j][1] + b1, 0.f);
                float v10 = fmaxf(acc[i][j][2] + b0, 0.f);
                float v11 = fmaxf(acc[i][j][3] + b1, 0.f);
                __nv_bfloat16 h00 = __float2bfloat16(v00), h01 = __float2bfloat16(v01);
                __nv_bfloat16 h10 = __float2bfloat16(v10), h11 = __float2bfloat16(v11);
                *(__nv_bfloat162*)(outH + r0 * NT + col) = __nv_bfloat162(h00, h01);
                *(__nv_bfloat162*)(outH + r1 * NT + col) = __nv_bfloat162(h10, h11);
                *(__nv_bfloat162*)(outL + r0 * NT + col) = __nv_bfloat162(
                    __float2bfloat16(v00 - __bfloat162float(h00)),
                    __float2bfloat16(v01 - __bfloat162float(h01)));
                *(__nv_bfloat162*)(outL + r1 * NT + col) = __nv_bfloat162(
                    __float2bfloat16(v10 - __bfloat162float(h10)),
                    __float2bfloat16(v11 - __bfloat162float(h11)));
            }
    } else {
        float* rs = (float*)smem;
        float* rq = rs + 512;
        float vsum[4][2], vsq[4][2];
#pragma unroll
        for (int i = 0; i < 4; i++) { vsum[i][0] = vsum[i][1] = vsq[i][0] = vsq[i][1] = 0.f; }
#pragma unroll
        for (int i = 0; i < 4; i++)
#pragma unroll
            for (int j = 0; j < FJ; j++) {
                int col = wn * WN + j * 8 + tg * 2;
                size_t r0 = rowblock + wm * 64 + i * 16 + g;
                size_t r1 = r0 + 8;
                float b0 = bias[col], b1 = bias[col + 1];
                float2 q0 = *(const float2*)(res + r0 * NT + col);
                float2 q1 = *(const float2*)(res + r1 * NT + col);
                float v00 = acc[i][j][0] + b0 + q0.x;
                float v01 = acc[i][j][1] + b1 + q0.y;
                float v10 = acc[i][j][2] + b0 + q1.x;
                float v11 = acc[i][j][3] + b1 + q1.y;
                acc[i][j][0] = v00; acc[i][j][1] = v01;
                acc[i][j][2] = v10; acc[i][j][3] = v11;
                vsum[i][0] += v00 + v01;  vsq[i][0] += v00 * v00 + v01 * v01;
                vsum[i][1] += v10 + v11;  vsq[i][1] += v10 * v10 + v11 * v11;
            }
#pragma unroll
        for (int i = 0; i < 4; i++)
#pragma unroll
            for (int hf = 0; hf < 2; hf++) {
                float s = vsum[i][hf], q = vsq[i][hf];
                s += __shfl_xor_sync(0xffffffffu, s, 1);
                s += __shfl_xor_sync(0xffffffffu, s, 2);
                q += __shfl_xor_sync(0xffffffffu, q, 1);
                q += __shfl_xor_sync(0xffffffffu, q, 2);
                if (tg == 0) {
                    int lr = wm * 64 + i * 16 + hf * 8 + g;
                    rs[lr * 4 + wn] = s;
                    rq[lr * 4 + wn] = q;
                }
            }
        __syncthreads();
        float mean[4][2], rstd[4][2];
#pragma unroll
        for (int i = 0; i < 4; i++)
#pragma unroll
            for (int hf = 0; hf < 2; hf++) {
                int lr = wm * 64 + i * 16 + hf * 8 + g;
                float S = rs[lr * 4] + rs[lr * 4 + 1] + rs[lr * 4 + 2] + rs[lr * 4 + 3];
                float Q = rq[lr * 4] + rq[lr * 4 + 1] + rq[lr * 4 + 2] + rq[lr * 4 + 3];
                float mn = S * (1.f / NT);
                mean[i][hf] = mn;
                rstd[i][hf] = rsqrtf(Q * (1.f / NT) - mn * mn + EPS_);
            }
#pragma unroll
        for (int i = 0; i < 4; i++)
#pragma unroll
            for (int j = 0; j < FJ; j++) {
                int col = wn * WN + j * 8 + tg * 2;
                size_t r0 = rowblock + wm * 64 + i * 16 + g;
                size_t r1 = r0 + 8;
                float w0 = lnw[col], w1 = lnw[col + 1];
                float c0 = lnb[col], c1 = lnb[col + 1];
                float v00 = (acc[i][j][0] - mean[i][0]) * rstd[i][0] * w0 + c0;
                float v01 = (acc[i][j][1] - mean[i][0]) * rstd[i][0] * w1 + c1;
                float v10 = (acc[i][j][2] - mean[i][1]) * rstd[i][1] * w0 + c0;
                float v11 = (acc[i][j][3] - mean[i][1]) * rstd[i][1] * w1 + c1;
                *(float2*)(outF + r0 * NT + col) = make_float2(v00, v01);
                *(float2*)(outF + r1 * NT + col) = make_float2(v10, v11);
                __nv_bfloat16 h00 = __float2bfloat16(v00), h01 = __float2bfloat16(v01);
                __nv_bfloat16 h10 = __float2bfloat16(v10), h11 = __float2bfloat16(v11);
                *(__nv_bfloat162*)(outH + r0 * NT + col) = __nv_bfloat162(h00, h01);
                *(__nv_bfloat162*)(outH + r1 * NT + col) = __nv_bfloat162(h10, h11);
                *(__nv_bfloat162*)(outL + r0 * NT + col) = __nv_bfloat162(
                    __float2bfloat16(v00 - __bfloat162float(h00)),
                    __float2bfloat16(v01 - __bfloat162float(h01)));
                *(__nv_bfloat162*)(outL + r1 * NT + col) = __nv_bfloat162(
                    __float2bfloat16(v10 - __bfloat162float(h10)),
                    __float2bfloat16(v11 - __bfloat162float(h11)));
            }
    }
}

// ---------------- merged flash attention: one CTA per (b,h), both q-blocks -
#define AQH 0
#define AQL 10240
#define AKH 20480
#define AKL 40960
#define AVH 61440
#define AVL 78336
#define ATTN_SMEM 95232

__global__ void __launch_bounds__(256, 2)
flash_attn(const float* __restrict__ qkv,
           __nv_bfloat16* __restrict__ outH, __nv_bfloat16* __restrict__ outL) {
    extern __shared__ char smem[];
    const uint32_t sb = smem_u32(smem);
    const int tid = threadIdx.x, lane = tid & 31;
    const int wrow = (tid >> 5) * 16;
    const int g = lane >> 2, tg = lane & 3;
    const int bh = blockIdx.x;
    const int b = bh >> 3, h = bh & 7;

    const float* kp = qkv + (size_t)BT_ * C_ + (size_t)(b * T_) * C_ + h * HS_;
    const float* vp = kp + (size_t)BT_ * C_;

    // ---- stage K, V (once per (b,h)) ----
#pragma unroll
    for (int it = 0; it < 8; it++) {
        int i = tid + it * 256;
        int r = i >> 3, c4 = i & 7;
        float4 f = *(const float4*)(kp + (size_t)r * C_ + c4 * 4);
        uint32_t o = r * 80 + c4 * 8;
        uint32_t h01 = packbf2(f.x, f.y), h23 = packbf2(f.z, f.w);
        *(uint32_t*)(smem + AKH + o)     = h01;
        *(uint32_t*)(smem + AKH + o + 4) = h23;
        __nv_bfloat162* p01 = (__nv_bfloat162*)&h01;
        __nv_bfloat162* p23 = (__nv_bfloat162*)&h23;
        *(uint32_t*)(smem + AKL + o) = packbf2(f.x - __bfloat162float(p01->x),
                                               f.y - __bfloat162float(p01->y));
        *(uint32_t*)(smem + AKL + o + 4) = packbf2(f.z - __bfloat162float(p23->x),
                                                   f.w - __bfloat162float(p23->y));
    }
#pragma unroll
    for (int it = 0; it < 8; it++) {
        int i = tid + it * 256;
        int r = i >> 3, c4 = i & 7;
        float4 f = *(const float4*)(vp + (size_t)r * C_ + c4 * 4);
        float vals[4] = {f.x, f.y, f.z, f.w};
#pragma unroll
        for (int m = 0; m < 4; m++) {
            int d = c4 * 4 + m;
            __nv_bfloat16 hi = __float2bfloat16(vals[m]);
            *(__nv_bfloat16*)(smem + AVH + d * 528 + r * 2) = hi;
            *(__nv_bfloat16*)(smem + AVL + d * 528 + r * 2) =
                __float2bfloat16(vals[m] - __bfloat162float(hi));
        }
    }

    for (int qb = 0; qb < 2; qb++) {
        // ---- stage Q for this q-block (region reused) ----
        const float* qp = qkv + ((size_t)(b * T_ + qb * 128)) * C_ + h * HS_;
        if (qb) __syncthreads();          // previous phase done with Q smem/frags
#pragma unroll
        for (int it = 0; it < 4; it++) {
            int i = tid + it * 256;
            int r = i >> 3, c4 = i & 7;
            float4 f = *(const float4*)(qp + (size_t)r * C_ + c4 * 4);
            f.x *= 0.0625f; f.y *= 0.0625f; f.z *= 0.0625f; f.w *= 0.0625f;
            uint32_t o = r * 80 + c4 * 8;
            uint32_t h01 = packbf2(f.x, f.y), h23 = packbf2(f.z, f.w);
            *(uint32_t*)(smem + AQH + o)     = h01;
            *(uint32_t*)(smem + AQH + o + 4) = h23;
            __nv_bfloat162* p01 = (__nv_bfloat162*)&h01;
            __nv_bfloat162* p23 = (__nv_bfloat162*)&h23;
            *(uint32_t*)(smem + AQL + o) = packbf2(f.x - __bfloat162float(p01->x),
                                                   f.y - __bfloat162float(p01->y));
            *(uint32_t*)(smem + AQL + o + 4) = packbf2(f.z - __bfloat162float(p23->x),
                                                       f.w - __bfloat162float(p23->y));
        }
        __syncthreads();

        uint32_t qf_h[2][4], qf_l[2][4];
#pragma unroll
        for (int ks = 0; ks < 2; ks++) {
            int r = wrow + (lane & 15);
            int hh = 2 * ks + (lane >> 4);
            ldmatrix_x4(qf_h[ks], sb + AQH + r * 80 + hh * 16);
            ldmatrix_x4(qf_l[ks], sb + AQL + r * 80 + hh * 16);
        }

        float m0 = -INFINITY, m1 = -INFINITY, l0 = 0.f, l1 = 0.f;
        float oacc[4][4];
#pragma unroll
        for (int nd = 0; nd < 4; nd++)
#pragma unroll
            for (int r = 0; r < 4; r++) oacc[nd][r] = 0.f;

        const int nch = (qb == 0) ? 2 : 4;
        const int qrow = qb * 128 + wrow + g;

        for (int ch = 0; ch < nch; ch++) {
            const int kbase = ch * 64;
            float sacc[8][4];
#pragma unroll
            for (int j = 0; j < 8; j++)
#pragma unroll
                for (int r = 0; r < 4; r++) sacc[j][r] = 0.f;
#pragma unroll
            for (int ks = 0; ks < 2; ks++) {
                uint32_t bh_[8][2], bl_[8][2];
#pragma unroll
                for (int j2 = 0; j2 < 4; j2++) {
                    int r = kbase + j2 * 16 + ((lane >> 4) & 1) * 8 + (lane & 7);
                    int hh = 2 * ks + ((lane >> 3) & 1);
                    uint32_t t4[4];
                    ldmatrix_x4(t4, sb + AKH + r * 80 + hh * 16);
                    bh_[2 * j2][0] = t4[0]; bh_[2 * j2][1] = t4[1];
                    bh_[2 * j2 + 1][0] = t4[2]; bh_[2 * j2 + 1][1] = t4[3];
                    ldmatrix_x4(t4, sb + AKL + r * 80 + hh * 16);
                    bl_[2 * j2][0] = t4[0]; bl_[2 * j2][1] = t4[1];
                    bl_[2 * j2 + 1][0] = t4[2]; bl_[2 * j2 + 1][1] = t4[3];
                }
#pragma unroll
                for (int j = 0; j < 8; j++) {
                    mma16816(sacc[j], qf_h[ks], bh_[j]);
                    mma16816(sacc[j], qf_h[ks], bl_[j]);
                    mma16816(sacc[j], qf_l[ks], bh_[j]);
                }
            }
            if (kbase + 63 > qb * 128 + wrow) {
#pragma unroll
                for (int j = 0; j < 8; j++) {
                    int key = kbase + j * 8 + tg * 2;
                    if (key     > qrow)     sacc[j][0] = -1e30f;
                    if (key + 1 > qrow)     sacc[j][1] = -1e30f;
                    if (key     > qrow + 8) sacc[j][2] = -1e30f;
                    if (key + 1 > qrow + 8) sacc[j][3] = -1e30f;
                }
            }
            uint32_t ph[8][2], pl[8][2];
            {
                float mx0 = -1e30f, mx1 = -1e30f;
#pragma unroll
                for (int j = 0; j < 8; j++) {
                    mx0 = fmaxf(mx0, fmaxf(sacc[j][0], sacc[j][1]));
                    mx1 = fmaxf(mx1, fmaxf(sacc[j][2], sacc[j][3]));
                }
                mx0 = fmaxf(mx0, __shfl_xor_sync(0xffffffffu, mx0, 1));
                mx0 = fmaxf(mx0, __shfl_xor_sync(0xffffffffu, mx0, 2));
                mx1 = fmaxf(mx1, __shfl_xor_sync(0xffffffffu, mx1, 1));
                mx1 = fmaxf(mx1, __shfl_xor_sync(0xffffffffu, mx1, 2));
                float mn0 = fmaxf(m0, mx0), mn1 = fmaxf(m1, mx1);
                float cr0 = __expf(m0 - mn0), cr1 = __expf(m1 - mn1);
                float rs0 = 0.f, rs1 = 0.f;
#pragma unroll
                for (int j = 0; j < 8; j++) {
                    float p0 = __expf(sacc[j][0] - mn0);
                    float p1 = __expf(sacc[j][1] - mn0);
                    float p2 = __expf(sacc[j][2] - mn1);
                    float p3 = __expf(sacc[j][3] - mn1);
                    rs0 += p0 + p1; rs1 += p2 + p3;
                    ph[j][0] = packbf2(p0, p1);
                    ph[j][1] = packbf2(p2, p3);
                    __nv_bfloat162* t0 = (__nv_bfloat162*)&ph[j][0];
                    __nv_bfloat162* t1 = (__nv_bfloat162*)&ph[j][1];
                    pl[j][0] = packbf2(p0 - __bfloat162float(t0->x),
                                       p1 - __bfloat162float(t0->y));
                    pl[j][1] = packbf2(p2 - __bfloat162float(t1->x),
                                       p3 - __bfloat162float(t1->y));
                }
                rs0 += __shfl_xor_sync(0xffffffffu, rs0, 1);
                rs0 += __shfl_xor_sync(0xffffffffu, rs0, 2);
                rs1 += __shfl_xor_sync(0xffffffffu, rs1, 1);
                rs1 += __shfl_xor_sync(0xffffffffu, rs1, 2);
                l0 = l0 * cr0 + rs0;  l1 = l1 * cr1 + rs1;
                m0 = mn0;  m1 = mn1;
#pragma unroll
                for (int nd = 0; nd < 4; nd++) {
                    oacc[nd][0] *= cr0; oacc[nd][1] *= cr0;
                    oacc[nd][2] *= cr1; oacc[nd][3] *= cr1;
                }
            }
#pragma unroll
            for (int kk = 0; kk < 4; kk++) {
                uint32_t pa_h[4] = {ph[2 * kk][0], ph[2 * kk][1],
                                    ph[2 * kk + 1][0], ph[2 * kk + 1][1]};
                uint32_t pa_l[4] = {pl[2 * kk][0], pl[2 * kk][1],
                                    pl[2 * kk + 1][0], pl[2 * kk + 1][1]};
                uint32_t vh[4][2], vl[4][2];
#pragma unroll
                for (int nd2 = 0; nd2 < 2; nd2++) {
                    int r = nd2 * 16 + ((lane >> 4) & 1) * 8 + (lane & 7);
                    int hh = (kbase >> 3) + 2 * kk + ((lane >> 3) & 1);
                    uint32_t t4[4];
                    ldmatrix_x4(t4, sb + AVH + r * 528 + hh * 16);
                    vh[2 * nd2][0] = t4[0]; vh[2 * nd2][1] = t4[1];
                    vh[2 * nd2 + 1][0] = t4[2]; vh[2 * nd2 + 1][1] = t4[3];
                    ldmatrix_x4(t4, sb + AVL + r * 528 + hh * 16);
                    vl[2 * nd2][0] = t4[0]; vl[2 * nd2][1] = t4[1];
                    vl[2 * nd2 + 1][0] = t4[2]; vl[2 * nd2 + 1][1] = t4[3];
                }
#pragma unroll
                for (int nd = 0; nd < 4; nd++) {
                    mma16816(oacc[nd], pa_h, vh[nd]);
                    mma16816(oacc[nd], pa_h, vl[nd]);
                    mma16816(oacc[nd], pa_l, vh[nd]);
                }
            }
        }

        float inv0 = 1.f / l0, inv1 = 1.f / l1;
        size_t r0 = (size_t)(b * T_) + qb * 128 + wrow + g, r1 = r0 + 8;
#pragma unroll
        for (int nd = 0; nd < 4; nd++) {
            int col = h * 32 + nd * 8 + tg * 2;
            float v00 = oacc[nd][0] * inv0, v01 = oacc[nd][1] * inv0;
            float v10 = oacc[nd][2] * inv1, v11 = oacc[nd][3] * inv1;
            __nv_bfloat16 h00 = __float2bfloat16(v00), h01 = __float2bfloat16(v01);
            __nv_bfloat16 h10 = __float2bfloat16(v10), h11 = __float2bfloat16(v11);
            *(__nv_bfloat162*)(outH + r0 * C_ + col) = __nv_bfloat162(h00, h01);
            *(__nv_bfloat162*)(outH + r1 * C_ + col) = __nv_bfloat162(h10, h11);
            *(__nv_bfloat162*)(outL + r0 * C_ + col) = __nv_bfloat162(
                __float2bfloat16(v00 - __bfloat162float(h00)),
                __float2bfloat16(v01 - __bfloat162float(h01)));
            *(__nv_bfloat162*)(outL + r1 * C_ + col) = __nv_bfloat162(
                __float2bfloat16(v10 - __bfloat162float(h10)),
                __float2bfloat16(v11 - __bfloat162float(h11)));
        }
    }
}

// ---------------- final layernorm ----------------
__global__ void add_ln_kernel(const float* __restrict__ x, const float* __restrict__ w,
                              const float* __restrict__ b,
                              __nv_bfloat16* __restrict__ outH, __nv_bfloat16* __restrict__ outL) {
    const int row = blockIdx.x, c = threadIdx.x;
    float v = x[(size_t)row * C_ + c];
    float s = v, s2 = v * v;
    __shared__ float sh1[8], sh2[8];
#pragma unroll
    for (int o = 16; o; o >>= 1) {
        s  += __shfl_xor_sync(0xffffffffu, s, o);
        s2 += __shfl_xor_sync(0xffffffffu, s2, o);
    }
    if ((c & 31) == 0) { sh1[c >> 5] = s; sh2[c >> 5] = s2; }
    __syncthreads();
    float S = 0.f, Q = 0.f;
#pragma unroll
    for (int i = 0; i < 8; i++) { S += sh1[i]; Q += sh2[i]; }
    float mean = S * (1.f / C_);
    float var  = Q * (1.f / C_) - mean * mean;
    float r = (v - mean) * rsqrtf(var + EPS_) * w[c] + b[c];
    size_t o = (size_t)row * C_ + c;
    __nv_bfloat16 hi = __float2bfloat16(r);
    outH[o] = hi;
    outL[o] = __float2bfloat16(r - __bfloat162float(hi));
}

// ---------------- NLL + loss ----------------
__global__ void nll_kernel(const float* __restrict__ logits, const int* __restrict__ tgt,
                           float* __restrict__ nll) {
    int warp = (blockIdx.x * blockDim.x + threadIdx.x) >> 5;
    int lane = threadIdx.x & 31;
    if (warp >= BT_) return;
    const float* l = logits + (size_t)warp * V_;
    float mx = -INFINITY;
    for (int c = lane; c < V_; c += 32) mx = fmaxf(mx, l[c]);
#pragma unroll
    for (int o = 16; o; o >>= 1) mx = fmaxf(mx, __shfl_xor_sync(0xffffffffu, mx, o));
    float s = 0.f;
    for (int c = lane; c < V_; c += 32) s += __expf(l[c] - mx);
#pragma unroll
    for (int o = 16; o; o >>= 1) s += __shfl_xor_sync(0xffffffffu, s, o);
    if (lane == 0) nll[warp] = -(l[tgt[warp]] - mx - __logf(s));
}
__global__ void reduce_loss_kernel(const float* __restrict__ nll, float* __restrict__ out) {
    __shared__ float sh[256];
    float s = 0.f;
    for (int i = threadIdx.x; i < BT_; i += 256) s += nll[i];
    sh[threadIdx.x] = s;
    __syncthreads();
    for (int st = 128; st; st >>= 1) {
        if (threadIdx.x < st) sh[threadIdx.x] += sh[threadIdx.x + st];
        __syncthreads();
    }
    if (threadIdx.x == 0) *out = sh[0] * (1.f / BT_);
}

// ---------------- host driver ----------------
extern "C" void kernel_launch(void* const* d_in, const int* in_sizes, int n_in,
                              void* d_out, int out_size) {
    const int*   idx     = (const int*)  d_in[0];
    const int*   target  = (const int*)  d_in[1];
    const float* tok_emb = (const float*)d_in[2];
    const float* pos_emb = (const float*)d_in[3];
    const float* Wq      = (const float*)d_in[4];
    const float* Wk      = (const float*)d_in[5];
    const float* Wv      = (const float*)d_in[6];
    const float* Wo      = (const float*)d_in[7];
    const float* bo      = (const float*)d_in[8];
    const float* W1      = (const float*)d_in[9];
    const float* b1      = (const float*)d_in[10];
    const float* W2      = (const float*)d_in[11];
    const float* b2_     = (const float*)d_in[12];
    const float* ln1_w   = (const float*)d_in[13];
    const float* ln1_b   = (const float*)d_in[14];
    const float* ln2_w   = (const float*)d_in[15];
    const float* ln2_b   = (const float*)d_in[16];
    const float* lnf_w   = (const float*)d_in[17];
    const float* lnf_b   = (const float*)d_in[18];
    const float* Wlm     = (const float*)d_in[19];
    const float* blm     = (const float*)d_in[20];

    float *px, *pqkv, *pnll;
    __nv_bfloat16 *pxh, *pxl, *pah, *pal, *phh, *phl, *pwh, *pwl;
    cudaGetSymbolAddress((void**)&px,   g_x);
    cudaGetSymbolAddress((void**)&pqkv, g_qkv);
    cudaGetSymbolAddress((void**)&pnll, g_nll);
    cudaGetSymbolAddress((void**)&pxh,  g_xh);
    cudaGetSymbolAddress((void**)&pxl,  g_xl);
    cudaGetSymbolAddress((void**)&pah,  g_ah);
    cudaGetSymbolAddress((void**)&pal,  g_al);
    cudaGetSymbolAddress((void**)&phh,  g_hh);
    cudaGetSymbolAddress((void**)&phl,  g_hl);
    cudaGetSymbolAddress((void**)&pwh,  g_wh);
    cudaGetSymbolAddress((void**)&pwl,  g_wl);

    cudaFuncSetAttribute(flash_attn, cudaFuncAttributeMaxDynamicSharedMemorySize, ATTN_SMEM);
    const int smem256 = 2 * (32768 + 2 * 256 * 128);
    const int smem128 = 2 * (32768 + 2 * 128 * 128);
    cudaFuncSetAttribute(hmma_gemm3<256, 0>, cudaFuncAttributeMaxDynamicSharedMemorySize, smem256);
    cudaFuncSetAttribute(hmma_gemm3<256, 1>, cudaFuncAttributeMaxDynamicSharedMemorySize, smem256);
    cudaFuncSetAttribute(hmma_gemm3<256, 2>, cudaFuncAttributeMaxDynamicSharedMemorySize, smem256);
    cudaFuncSetAttribute(hmma_gemm3<128, 0>, cudaFuncAttributeMaxDynamicSharedMemorySize, smem128);

    convw_all<<<dim3(256, 37), 256>>>(Wq, Wk, Wv, Wo, W1, W2, Wlm, pwh, pwl);
    embed_kernel<<<BT_, C_>>>(idx, tok_emb, pos_emb, px, pxh, pxl);

    const size_t QKV_OSTRIDE = (size_t)BT_ * C_;
    const size_t QKV_WSTRIDE = (size_t)6 * WMAT_ELEMS;

    for (int l = 0; l < L_; l++) {
        hmma_gemm3<256, 0><<<dim3(128, 3), 256, smem256>>>(pxh, pxl,
            pwh + WOFF(0, l), pwl + WOFF(0, l), QKV_WSTRIDE,
            pqkv, QKV_OSTRIDE, nullptr, nullptr, nullptr, nullptr, nullptr, nullptr, C_);
        flash_attn<<<B_ * H_, 256, ATTN_SMEM>>>(pqkv, pah, pal);
        hmma_gemm3<256, 2><<<dim3(128, 1), 256, smem256>>>(pah, pal,
            pwh + WOFF(3, l), pwl + WOFF(3, l), 0,
            px, 0, pxh, pxl, bo + l * C_, px, ln1_w + l * C_, ln1_b + l * C_, C_);
        hmma_gemm3<256, 1><<<dim3(128, 1), 256, smem256>>>(pxh, pxl,
            pwh + WOFF(4, l), pwl + WOFF(4, l), 0,
            nullptr, 0, phh, phl, b1 + l * C_, nullptr, nullptr, nullptr, C_);
        hmma_gemm3<256, 2><<<dim3(128, 1), 256, smem256>>>(phh, phl,
            pwh + WOFF(5, l), pwl + WOFF(5, l), 0,
            px, 0, pxh, pxl, b2_ + l * C_, px, ln2_w + l * C_, ln2_b + l * C_, C_);
    }
    add_ln_kernel<<<BT_, C_>>>(px, lnf_w, lnf_b, pxh, pxl);

    float* logits = (out_size >= BT_ * V_) ? (float*)d_out : pqkv;
    hmma_gemm3<128, 0><<<dim3(128, 1), 256, smem128>>>(pxh, pxl,
        pwh + WOFF_LM, pwl + WOFF_LM, 0,
        logits, 0, nullptr, nullptr, blm, nullptr, nullptr, nullptr, V_);

    nll_kernel<<<(BT_ * 32 + 255) / 256, 256>>>(logits, target, pnll);

    float* loss_dst = nullptr;
    if (out_size == 1)            loss_dst = (float*)d_out;
    else if (out_size > BT_ * V_) loss_dst = (float*)d_out + BT_ * V_;
    if (loss_dst) reduce_loss_kernel<<<1, 256>>>(pnll, loss_dst);
}

// round 15
// speedup vs baseline: 1.1005x; 1.0216x over previous
#include <cuda_runtime.h>
#include <cuda_bf16.h>
#include <cstdint>
#include <math.h>

#define B_  64
#define T_  256
#define C_  256
#define H_  8
#define HS_ 32
#define L_  6
#define V_  96
#define BT_ (B_ * T_)
#define EPS_ 1e-5f

__device__ __align__(16) float g_x  [BT_ * C_];
__device__ __align__(16) float g_qkv[3 * BT_ * C_];
__device__ __align__(16) float g_nll[BT_];

__device__ __align__(16) __nv_bfloat16 g_xh [BT_ * C_];
__device__ __align__(16) __nv_bfloat16 g_xl [BT_ * C_];
__device__ __align__(16) __nv_bfloat16 g_ah [BT_ * C_];
__device__ __align__(16) __nv_bfloat16 g_al [BT_ * C_];
__device__ __align__(16) __nv_bfloat16 g_hh [BT_ * C_];
__device__ __align__(16) __nv_bfloat16 g_hl [BT_ * C_];

#define WMAT_ELEMS (C_ * C_)
#define WLM_ROWS   128
#define W_TOTAL    (36 * WMAT_ELEMS + WLM_ROWS * C_)
__device__ __align__(16) __nv_bfloat16 g_wh[W_TOTAL];
__device__ __align__(16) __nv_bfloat16 g_wl[W_TOTAL];
#define WOFF(t, l) ((size_t)((t) * 6 + (l)) * WMAT_ELEMS)
#define WOFF_LM    ((size_t)36 * WMAT_ELEMS)

// ---------------- helpers ----------------
__device__ __forceinline__ uint32_t smem_u32(const void* p) {
    uint32_t a;
    asm("{ .reg .u64 t; cvta.to.shared.u64 t, %1; cvt.u32.u64 %0, t; }" : "=r"(a) : "l"(p));
    return a;
}
__device__ __forceinline__ void cp_async16(uint32_t dst, const void* src) {
    asm volatile("cp.async.cg.shared.global [%0], [%1], 16;" :: "r"(dst), "l"(src) : "memory");
}
__device__ __forceinline__ void cp_commit() { asm volatile("cp.async.commit_group;" ::: "memory"); }
template <int N>
__device__ __forceinline__ void cp_wait() {
    asm volatile("cp.async.wait_group %0;" :: "n"(N) : "memory");
}
__device__ __forceinline__ void ldmatrix_x4(uint32_t* r, uint32_t addr) {
    asm volatile("ldmatrix.sync.aligned.m8n8.x4.shared.b16 {%0,%1,%2,%3}, [%4];"
                 : "=r"(r[0]), "=r"(r[1]), "=r"(r[2]), "=r"(r[3]) : "r"(addr));
}
__device__ __forceinline__ void mma16816(float* c, const uint32_t* a, const uint32_t* b) {
    asm volatile("mma.sync.aligned.m16n8k16.row.col.f32.bf16.bf16.f32 "
                 "{%0,%1,%2,%3}, {%4,%5,%6,%7}, {%8,%9}, {%0,%1,%2,%3};"
                 : "+f"(c[0]), "+f"(c[1]), "+f"(c[2]), "+f"(c[3])
                 : "r"(a[0]), "r"(a[1]), "r"(a[2]), "r"(a[3]), "r"(b[0]), "r"(b[1]));
}
__device__ __forceinline__ uint32_t packbf2(float a, float b) {
    __nv_bfloat162 t(__float2bfloat16(a), __float2bfloat16(b));
    return *(uint32_t*)&t;
}

// ---------------- weight transpose + hi/lo ----------------
__global__ void convw_all(const float* __restrict__ Wq, const float* __restrict__ Wk,
                          const float* __restrict__ Wv, const float* __restrict__ Wo,
                          const float* __restrict__ W1, const float* __restrict__ W2,
                          const float* __restrict__ Wlm,
                          __nv_bfloat16* __restrict__ hi, __nv_bfloat16* __restrict__ lo) {
    const int mat = blockIdx.y;
    const int i = blockIdx.x * 256 + threadIdx.x;
    float v;
    size_t o;
    if (mat < 36) {
        if (i >= WMAT_ELEMS) return;
        const float* srcs[6] = {Wq, Wk, Wv, Wo, W1, W2};
        const float* s = srcs[mat / 6] + (size_t)(mat % 6) * WMAT_ELEMS;
        int n = i >> 8, k = i & 255;
        v = s[(size_t)k * 256 + n];
        o = (size_t)mat * WMAT_ELEMS + i;
    } else {
        if (i >= WLM_ROWS * C_) return;
        int n = i >> 8, k = i & 255;
        v = (n < V_) ? Wlm[(size_t)k * V_ + n] : 0.f;
        o = WOFF_LM + i;
    }
    __nv_bfloat16 h = __float2bfloat16(v);
    hi[o] = h;
    lo[o] = __float2bfloat16(v - __bfloat162float(h));
}

// ---------------- embedding ----------------
__global__ void embed_kernel(const int* __restrict__ idx, const float* __restrict__ tok_emb,
                             const float* __restrict__ pos_emb, float* __restrict__ x,
                             __nv_bfloat16* __restrict__ xh, __nv_bfloat16* __restrict__ xl) {
    int bt = blockIdx.x, c = threadIdx.x;
    float v = tok_emb[idx[bt] * C_ + c] + pos_emb[(bt % T_) * C_ + c];
    size_t o = (size_t)bt * C_ + c;
    x[o] = v;
    __nv_bfloat16 h = __float2bfloat16(v);
    xh[o] = h;
    xl[o] = __float2bfloat16(v - __bfloat162float(h));
}

// ---------------- HMMA GEMM (round-6 core) ----------------
template <int NT, int MODE>
__global__ void __launch_bounds__(256)
hmma_gemm3(const __nv_bfloat16* __restrict__ Ah, const __nv_bfloat16* __restrict__ Al,
           const __nv_bfloat16* __restrict__ BhBase, const __nv_bfloat16* __restrict__ BlBase,
           size_t wstride, float* outF, size_t ostride,
           __nv_bfloat16* __restrict__ outH, __nv_bfloat16* __restrict__ outL,
           const float* __restrict__ bias, const float* __restrict__ res,
           const float* __restrict__ lnw, const float* __restrict__ lnb, int Nout) {
    extern __shared__ char smem[];
    const uint32_t sb = smem_u32(smem);
    constexpr int AHo = 0, ALo = 16384, BHo = 32768, BLo = 32768 + NT * 128;
    constexpr int STAGE = 32768 + 2 * NT * 128;
    constexpr int NCH   = 2048 + NT * 16;
    constexpr int WN  = NT / 4;
    constexpr int FJ  = WN / 8;
    constexpr int FJ2 = WN / 16;

    const int tid  = threadIdx.x;
    const int lane = tid & 31;
    const int w    = tid >> 5;
    const int wm   = w & 1;
    const int wn   = w >> 1;

    const size_t rowblock = (size_t)blockIdx.x * 128;
    const __nv_bfloat16* Bh = BhBase + blockIdx.y * wstride;
    const __nv_bfloat16* Bl = BlBase + blockIdx.y * wstride;
    if (MODE == 0) outF += blockIdx.y * ostride;

    float acc[4][FJ][4];
#pragma unroll
    for (int i = 0; i < 4; i++)
#pragma unroll
        for (int j = 0; j < FJ; j++)
#pragma unroll
            for (int r = 0; r < 4; r++) acc[i][j][r] = 0.f;

    auto load_stage = [&](int s, int buf) {
        const int k0 = s * 64;
        const uint32_t base = sb + buf * STAGE;
#pragma unroll
        for (int c = tid; c < NCH; c += 256) {
            if (c < 1024) {
                int r = c >> 3, h = c & 7;
                cp_async16(base + AHo + r * 128 + 16 * (h ^ (r & 7)),
                           Ah + (rowblock + r) * 256 + k0 + h * 8);
            } else if (c < 2048) {
                int cc = c - 1024;
                int r = cc >> 3, h = cc & 7;
                cp_async16(base + ALo + r * 128 + 16 * (h ^ (r & 7)),
                           Al + (rowblock + r) * 256 + k0 + h * 8);
            } else if (c < 2048 + NT * 8) {
                int cc = c - 2048;
                int r = cc >> 3, h = cc & 7;
                cp_async16(base + BHo + r * 128 + 16 * (h ^ (r & 7)),
                           Bh + (size_t)r * 256 + k0 + h * 8);
            } else {
                int cc = c - 2048 - NT * 8;
                int r = cc >> 3, h = cc & 7;
                cp_async16(base + BLo + r * 128 + 16 * (h ^ (r & 7)),
                           Bl + (size_t)r * 256 + k0 + h * 8);
            }
        }
        cp_commit();
    };

    load_stage(0, 0);
    for (int s = 0; s < 4; s++) {
        if (s < 3) { load_stage(s + 1, (s + 1) & 1); cp_wait<1>(); }
        else       { cp_wait<0>(); }
        __syncthreads();
        const uint32_t base = sb + (s & 1) * STAGE;
#pragma unroll
        for (int ks = 0; ks < 4; ks++) {
            uint32_t ah[4][4], al[4][4];
#pragma unroll
            for (int i = 0; i < 4; i++) {
                int r = wm * 64 + i * 16 + (lane & 15);
                int hh = 2 * ks + (lane >> 4);
                uint32_t off = r * 128 + 16 * (hh ^ (r & 7));
                ldmatrix_x4(ah[i], base + AHo + off);
                ldmatrix_x4(al[i], base + ALo + off);
            }
#pragma unroll
            for (int j2 = 0; j2 < FJ2; j2++) {
                int r = wn * WN + j2 * 16 + ((lane >> 4) & 1) * 8 + (lane & 7);
                int hh = 2 * ks + ((lane >> 3) & 1);
                uint32_t off = r * 128 + 16 * (hh ^ (r & 7));
                uint32_t bh4[4], bl4[4];
                ldmatrix_x4(bh4, base + BHo + off);
                ldmatrix_x4(bl4, base + BLo + off);
#pragma unroll
                for (int i = 0; i < 4; i++) {
                    mma16816(acc[i][2 * j2],     ah[i], bh4);
                    mma16816(acc[i][2 * j2 + 1], ah[i], bh4 + 2);
                    mma16816(acc[i][2 * j2],     ah[i], bl4);
                    mma16816(acc[i][2 * j2 + 1], ah[i], bl4 + 2);
                    mma16816(acc[i][2 * j2],     al[i], bh4);
                    mma16816(acc[i][2 * j2 + 1], al[i], bh4 + 2);
                }
            }
        }
        __syncthreads();
    }

    const int g  = lane >> 2;
    const int tg = lane & 3;

    if (MODE == 0) {
#pragma unroll
        for (int i = 0; i < 4; i++)
#pragma unroll
            for (int j = 0; j < FJ; j++) {
                int col = wn * WN + j * 8 + tg * 2;
                if (col >= Nout) continue;
                size_t r0 = rowblock + wm * 64 + i * 16 + g;
                size_t r1 = r0 + 8;
                float b0 = bias ? bias[col] : 0.f;
                float b1 = bias ? bias[col + 1] : 0.f;
                *(float2*)(outF + r0 * Nout + col) =
                    make_float2(acc[i][j][0] + b0, acc[i][j][1] + b1);
                *(float2*)(outF + r1 * Nout + col) =
                    make_float2(acc[i][j][2] + b0, acc[i][j][3] + b1);
            }
    } else if (MODE == 1) {
#pragma unroll
        for (int i = 0; i < 4; i++)
#pragma unroll
            for (int j = 0; j < FJ; j++) {
                int col = wn * WN + j * 8 + tg * 2;
                size_t r0 = rowblock + wm * 64 + i * 16 + g;
                size_t r1 = r0 + 8;
                float b0 = bias[col], b1 = bias[col + 1];
                float v00 = fmaxf(acc[i][j][0] + b0, 0.f);
                float v01 = fmaxf(acc[i][j][1] + b1, 0.f);
                float v10 = fmaxf(acc[i][j][2] + b0, 0.f);
                float v11 = fmaxf(acc[i][j][3] + b1, 0.f);
                __nv_bfloat16 h00 = __float2bfloat16(v00), h01 = __float2bfloat16(v01);
                __nv_bfloat16 h10 = __float2bfloat16(v10), h11 = __float2bfloat16(v11);
                *(__nv_bfloat162*)(outH + r0 * NT + col) = __nv_bfloat162(h00, h01);
                *(__nv_bfloat162*)(outH + r1 * NT + col) = __nv_bfloat162(h10, h11);
                *(__nv_bfloat162*)(outL + r0 * NT + col) = __nv_bfloat162(
                    __float2bfloat16(v00 - __bfloat162float(h00)),
                    __float2bfloat16(v01 - __bfloat162float(h01)));
                *(__nv_bfloat162*)(outL + r1 * NT + col) = __nv_bfloat162(
                    __float2bfloat16(v10 - __bfloat162float(h10)),
                    __float2bfloat16(v11 - __bfloat162float(h11)));
            }
    } else {
        float* rs = (float*)smem;
        float* rq = rs + 512;
        float vsum[4][2], vsq[4][2];
#pragma unroll
        for (int i = 0; i < 4; i++) { vsum[i][0] = vsum[i][1] = vsq[i][0] = vsq[i][1] = 0.f; }
#pragma unroll
        for (int i = 0; i < 4; i++)
#pragma unroll
            for (int j = 0; j < FJ; j++) {
                int col = wn * WN + j * 8 + tg * 2;
                size_t r0 = rowblock + wm * 64 + i * 16 + g;
                size_t r1 = r0 + 8;
                float b0 = bias[col], b1 = bias[col + 1];
                float2 q0 = *(const float2*)(res + r0 * NT + col);
                float2 q1 = *(const float2*)(res + r1 * NT + col);
                float v00 = acc[i][j][0] + b0 + q0.x;
                float v01 = acc[i][j][1] + b1 + q0.y;
                float v10 = acc[i][j][2] + b0 + q1.x;
                float v11 = acc[i][j][3] + b1 + q1.y;
                acc[i][j][0] = v00; acc[i][j][1] = v01;
                acc[i][j][2] = v10; acc[i][j][3] = v11;
                vsum[i][0] += v00 + v01;  vsq[i][0] += v00 * v00 + v01 * v01;
                vsum[i][1] += v10 + v11;  vsq[i][1] += v10 * v10 + v11 * v11;
            }
#pragma unroll
        for (int i = 0; i < 4; i++)
#pragma unroll
            for (int hf = 0; hf < 2; hf++) {
                float s = vsum[i][hf], q = vsq[i][hf];
                s += __shfl_xor_sync(0xffffffffu, s, 1);
                s += __shfl_xor_sync(0xffffffffu, s, 2);
                q += __shfl_xor_sync(0xffffffffu, q, 1);
                q += __shfl_xor_sync(0xffffffffu, q, 2);
                if (tg == 0) {
                    int lr = wm * 64 + i * 16 + hf * 8 + g;
                    rs[lr * 4 + wn] = s;
                    rq[lr * 4 + wn] = q;
                }
            }
        __syncthreads();
        float mean[4][2], rstd[4][2];
#pragma unroll
        for (int i = 0; i < 4; i++)
#pragma unroll
            for (int hf = 0; hf < 2; hf++) {
                int lr = wm * 64 + i * 16 + hf * 8 + g;
                float S = rs[lr * 4] + rs[lr * 4 + 1] + rs[lr * 4 + 2] + rs[lr * 4 + 3];
                float Q = rq[lr * 4] + rq[lr * 4 + 1] + rq[lr * 4 + 2] + rq[lr * 4 + 3];
                float mn = S * (1.f / NT);
                mean[i][hf] = mn;
                rstd[i][hf] = rsqrtf(Q * (1.f / NT) - mn * mn + EPS_);
            }
#pragma unroll
        for (int i = 0; i < 4; i++)
#pragma unroll
            for (int j = 0; j < FJ; j++) {
                int col = wn * WN + j * 8 + tg * 2;
                size_t r0 = rowblock + wm * 64 + i * 16 + g;
                size_t r1 = r0 + 8;
                float w0 = lnw[col], w1 = lnw[col + 1];
                float c0 = lnb[col], c1 = lnb[col + 1];
                float v00 = (acc[i][j][0] - mean[i][0]) * rstd[i][0] * w0 + c0;
                float v01 = (acc[i][j][1] - mean[i][0]) * rstd[i][0] * w1 + c1;
                float v10 = (acc[i][j][2] - mean[i][1]) * rstd[i][1] * w0 + c0;
                float v11 = (acc[i][j][3] - mean[i][1]) * rstd[i][1] * w1 + c1;
                *(float2*)(outF + r0 * NT + col) = make_float2(v00, v01);
                *(float2*)(outF + r1 * NT + col) = make_float2(v10, v11);
                __nv_bfloat16 h00 = __float2bfloat16(v00), h01 = __float2bfloat16(v01);
                __nv_bfloat16 h10 = __float2bfloat16(v10), h11 = __float2bfloat16(v11);
                *(__nv_bfloat162*)(outH + r0 * NT + col) = __nv_bfloat162(h00, h01);
                *(__nv_bfloat162*)(outH + r1 * NT + col) = __nv_bfloat162(h10, h11);
                *(__nv_bfloat162*)(outL + r0 * NT + col) = __nv_bfloat162(
                    __float2bfloat16(v00 - __bfloat162float(h00)),
                    __float2bfloat16(v01 - __bfloat162float(h01)));
                *(__nv_bfloat162*)(outL + r1 * NT + col) = __nv_bfloat162(
                    __float2bfloat16(v10 - __bfloat162float(h10)),
                    __float2bfloat16(v11 - __bfloat162float(h11)));
            }
    }
}

// ---------------- merged flash attention + causal chunk skip ----------------
#define AQH 0
#define AQL 10240
#define AKH 20480
#define AKL 40960
#define AVH 61440
#define AVL 78336
#define ATTN_SMEM 95232

__global__ void __launch_bounds__(256, 2)
flash_attn(const float* __restrict__ qkv,
           __nv_bfloat16* __restrict__ outH, __nv_bfloat16* __restrict__ outL) {
    extern __shared__ char smem[];
    const uint32_t sb = smem_u32(smem);
    const int tid = threadIdx.x, lane = tid & 31;
    const int wrow = (tid >> 5) * 16;
    const int g = lane >> 2, tg = lane & 3;
    const int bh = blockIdx.x;
    const int b = bh >> 3, h = bh & 7;

    const float* kp = qkv + (size_t)BT_ * C_ + (size_t)(b * T_) * C_ + h * HS_;
    const float* vp = kp + (size_t)BT_ * C_;

#pragma unroll
    for (int it = 0; it < 8; it++) {
        int i = tid + it * 256;
        int r = i >> 3, c4 = i & 7;
        float4 f = *(const float4*)(kp + (size_t)r * C_ + c4 * 4);
        uint32_t o = r * 80 + c4 * 8;
        uint32_t h01 = packbf2(f.x, f.y), h23 = packbf2(f.z, f.w);
        *(uint32_t*)(smem + AKH + o)     = h01;
        *(uint32_t*)(smem + AKH + o + 4) = h23;
        __nv_bfloat162* p01 = (__nv_bfloat162*)&h01;
        __nv_bfloat162* p23 = (__nv_bfloat162*)&h23;
        *(uint32_t*)(smem + AKL + o) = packbf2(f.x - __bfloat162float(p01->x),
                                               f.y - __bfloat162float(p01->y));
        *(uint32_t*)(smem + AKL + o + 4) = packbf2(f.z - __bfloat162float(p23->x),
                                                   f.w - __bfloat162float(p23->y));
    }
#pragma unroll
    for (int it = 0; it < 8; it++) {
        int i = tid + it * 256;
        int r = i >> 3, c4 = i & 7;
        float4 f = *(const float4*)(vp + (size_t)r * C_ + c4 * 4);
        float vals[4] = {f.x, f.y, f.z, f.w};
#pragma unroll
        for (int m = 0; m < 4; m++) {
            int d = c4 * 4 + m;
            __nv_bfloat16 hi = __float2bfloat16(vals[m]);
            *(__nv_bfloat16*)(smem + AVH + d * 528 + r * 2) = hi;
            *(__nv_bfloat16*)(smem + AVL + d * 528 + r * 2) =
                __float2bfloat16(vals[m] - __bfloat162float(hi));
        }
    }

    for (int qb = 0; qb < 2; qb++) {
        const float* qp = qkv + ((size_t)(b * T_ + qb * 128)) * C_ + h * HS_;
        if (qb) __syncthreads();
#pragma unroll
        for (int it = 0; it < 4; it++) {
            int i = tid + it * 256;
            int r = i >> 3, c4 = i & 7;
            float4 f = *(const float4*)(qp + (size_t)r * C_ + c4 * 4);
            f.x *= 0.0625f; f.y *= 0.0625f; f.z *= 0.0625f; f.w *= 0.0625f;
            uint32_t o = r * 80 + c4 * 8;
            uint32_t h01 = packbf2(f.x, f.y), h23 = packbf2(f.z, f.w);
            *(uint32_t*)(smem + AQH + o)     = h01;
            *(uint32_t*)(smem + AQH + o + 4) = h23;
            __nv_bfloat162* p01 = (__nv_bfloat162*)&h01;
            __nv_bfloat162* p23 = (__nv_bfloat162*)&h23;
            *(uint32_t*)(smem + AQL + o) = packbf2(f.x - __bfloat162float(p01->x),
                                                   f.y - __bfloat162float(p01->y));
            *(uint32_t*)(smem + AQL + o + 4) = packbf2(f.z - __bfloat162float(p23->x),
                                                       f.w - __bfloat162float(p23->y));
        }
        __syncthreads();

        uint32_t qf_h[2][4], qf_l[2][4];
#pragma unroll
        for (int ks = 0; ks < 2; ks++) {
            int r = wrow + (lane & 15);
            int hh = 2 * ks + (lane >> 4);
            ldmatrix_x4(qf_h[ks], sb + AQH + r * 80 + hh * 16);
            ldmatrix_x4(qf_l[ks], sb + AQL + r * 80 + hh * 16);
        }

        float m0 = -INFINITY, m1 = -INFINITY, l0 = 0.f, l1 = 0.f;
        float oacc[4][4];
#pragma unroll
        for (int nd = 0; nd < 4; nd++)
#pragma unroll
            for (int r = 0; r < 4; r++) oacc[nd][r] = 0.f;

        const int nch = (qb == 0) ? 2 : 4;
        const int qrow = qb * 128 + wrow + g;
        const int warpmax = qb * 128 + wrow + 15;   // max query row of this warp

        for (int ch = 0; ch < nch; ch++) {
            const int kbase = ch * 64;
            if (kbase > warpmax) break;   // chunk fully masked for this warp (exact skip)
            float sacc[8][4];
#pragma unroll
            for (int j = 0; j < 8; j++)
#pragma unroll
                for (int r = 0; r < 4; r++) sacc[j][r] = 0.f;
#pragma unroll
            for (int ks = 0; ks < 2; ks++) {
                uint32_t bh_[8][2], bl_[8][2];
#pragma unroll
                for (int j2 = 0; j2 < 4; j2++) {
                    int r = kbase + j2 * 16 + ((lane >> 4) & 1) * 8 + (lane & 7);
                    int hh = 2 * ks + ((lane >> 3) & 1);
                    uint32_t t4[4];
                    ldmatrix_x4(t4, sb + AKH + r * 80 + hh * 16);
                    bh_[2 * j2][0] = t4[0]; bh_[2 * j2][1] = t4[1];
                    bh_[2 * j2 + 1][0] = t4[2]; bh_[2 * j2 + 1][1] = t4[3];
                    ldmatrix_x4(t4, sb + AKL + r * 80 + hh * 16);
                    bl_[2 * j2][0] = t4[0]; bl_[2 * j2][1] = t4[1];
                    bl_[2 * j2 + 1][0] = t4[2]; bl_[2 * j2 + 1][1] = t4[3];
                }
#pragma unroll
                for (int j = 0; j < 8; j++) {
                    mma16816(sacc[j], qf_h[ks], bh_[j]);
                    mma16816(sacc[j], qf_h[ks], bl_[j]);
                    mma16816(sacc[j], qf_l[ks], bh_[j]);
                }
            }
            if (kbase + 63 > qb * 128 + wrow) {
#pragma unroll
                for (int j = 0; j < 8; j++) {
                    int key = kbase + j * 8 + tg * 2;
                    if (key     > qrow)     sacc[j][0] = -1e30f;
                    if (key + 1 > qrow)     sacc[j][1] = -1e30f;
                    if (key     > qrow + 8) sacc[j][2] = -1e30f;
                    if (key + 1 > qrow + 8) sacc[j][3] = -1e30f;
                }
            }
            uint32_t ph[8][2], pl[8][2];
            {
                float mx0 = -1e30f, mx1 = -1e30f;
#pragma unroll
                for (int j = 0; j < 8; j++) {
                    mx0 = fmaxf(mx0, fmaxf(sacc[j][0], sacc[j][1]));
                    mx1 = fmaxf(mx1, fmaxf(sacc[j][2], sacc[j][3]));
                }
                mx0 = fmaxf(mx0, __shfl_xor_sync(0xffffffffu, mx0, 1));
                mx0 = fmaxf(mx0, __shfl_xor_sync(0xffffffffu, mx0, 2));
                mx1 = fmaxf(mx1, __shfl_xor_sync(0xffffffffu, mx1, 1));
                mx1 = fmaxf(mx1, __shfl_xor_sync(0xffffffffu, mx1, 2));
                float mn0 = fmaxf(m0, mx0), mn1 = fmaxf(m1, mx1);
                float cr0 = __expf(m0 - mn0), cr1 = __expf(m1 - mn1);
                float rs0 = 0.f, rs1 = 0.f;
#pragma unroll
                for (int j = 0; j < 8; j++) {
                    float p0 = __expf(sacc[j][0] - mn0);
                    float p1 = __expf(sacc[j][1] - mn0);
                    float p2 = __expf(sacc[j][2] - mn1);
                    float p3 = __expf(sacc[j][3] - mn1);
                    rs0 += p0 + p1; rs1 += p2 + p3;
                    ph[j][0] = packbf2(p0, p1);
                    ph[j][1] = packbf2(p2, p3);
                    __nv_bfloat162* t0 = (__nv_bfloat162*)&ph[j][0];
                    __nv_bfloat162* t1 = (__nv_bfloat162*)&ph[j][1];
                    pl[j][0] = packbf2(p0 - __bfloat162float(t0->x),
                                       p1 - __bfloat162float(t0->y));
                    pl[j][1] = packbf2(p2 - __bfloat162float(t1->x),
                                       p3 - __bfloat162float(t1->y));
                }
                rs0 += __shfl_xor_sync(0xffffffffu, rs0, 1);
                rs0 += __shfl_xor_sync(0xffffffffu, rs0, 2);
                rs1 += __shfl_xor_sync(0xffffffffu, rs1, 1);
                rs1 += __shfl_xor_sync(0xffffffffu, rs1, 2);
                l0 = l0 * cr0 + rs0;  l1 = l1 * cr1 + rs1;
                m0 = mn0;  m1 = mn1;
#pragma unroll
                for (int nd = 0; nd < 4; nd++) {
                    oacc[nd][0] *= cr0; oacc[nd][1] *= cr0;
                    oacc[nd][2] *= cr1; oacc[nd][3] *= cr1;
                }
            }
#pragma unroll
            for (int kk = 0; kk < 4; kk++) {
                uint32_t pa_h[4] = {ph[2 * kk][0], ph[2 * kk][1],
                                    ph[2 * kk + 1][0], ph[2 * kk + 1][1]};
                uint32_t pa_l[4] = {pl[2 * kk][0], pl[2 * kk][1],
                                    pl[2 * kk + 1][0], pl[2 * kk + 1][1]};
                uint32_t vh[4][2], vl[4][2];
#pragma unroll
                for (int nd2 = 0; nd2 < 2; nd2++) {
                    int r = nd2 * 16 + ((lane >> 4) & 1) * 8 + (lane & 7);
                    int hh = (kbase >> 3) + 2 * kk + ((lane >> 3) & 1);
                    uint32_t t4[4];
                    ldmatrix_x4(t4, sb + AVH + r * 528 + hh * 16);
                    vh[2 * nd2][0] = t4[0]; vh[2 * nd2][1] = t4[1];
                    vh[2 * nd2 + 1][0] = t4[2]; vh[2 * nd2 + 1][1] = t4[3];
                    ldmatrix_x4(t4, sb + AVL + r * 528 + hh * 16);
                    vl[2 * nd2][0] = t4[0]; vl[2 * nd2][1] = t4[1];
                    vl[2 * nd2 + 1][0] = t4[2]; vl[2 * nd2 + 1][1] = t4[3];
                }
#pragma unroll
                for (int nd = 0; nd < 4; nd++) {
                    mma16816(oacc[nd], pa_h, vh[nd]);
                    mma16816(oacc[nd], pa_h, vl[nd]);
                    mma16816(oacc[nd], pa_l, vh[nd]);
                }
            }
        }

        float inv0 = 1.f / l0, inv1 = 1.f / l1;
        size_t r0 = (size_t)(b * T_) + qb * 128 + wrow + g, r1 = r0 + 8;
#pragma unroll
        for (int nd = 0; nd < 4; nd++) {
            int col = h * 32 + nd * 8 + tg * 2;
            float v00 = oacc[nd][0] * inv0, v01 = oacc[nd][1] * inv0;
            float v10 = oacc[nd][2] * inv1, v11 = oacc[nd][3] * inv1;
            __nv_bfloat16 h00 = __float2bfloat16(v00), h01 = __float2bfloat16(v01);
            __nv_bfloat16 h10 = __float2bfloat16(v10), h11 = __float2bfloat16(v11);
            *(__nv_bfloat162*)(outH + r0 * C_ + col) = __nv_bfloat162(h00, h01);
            *(__nv_bfloat162*)(outH + r1 * C_ + col) = __nv_bfloat162(h10, h11);
            *(__nv_bfloat162*)(outL + r0 * C_ + col) = __nv_bfloat162(
                __float2bfloat16(v00 - __bfloat162float(h00)),
                __float2bfloat16(v01 - __bfloat162float(h01)));
            *(__nv_bfloat162*)(outL + r1 * C_ + col) = __nv_bfloat162(
                __float2bfloat16(v10 - __bfloat162float(h10)),
                __float2bfloat16(v11 - __bfloat162float(h11)));
        }
    }
}

// ---------------- final layernorm ----------------
__global__ void add_ln_kernel(const float* __restrict__ x, const float* __restrict__ w,
                              const float* __restrict__ b,
                              __nv_bfloat16* __restrict__ outH, __nv_bfloat16* __restrict__ outL) {
    const int row = blockIdx.x, c = threadIdx.x;
    float v = x[(size_t)row * C_ + c];
    float s = v, s2 = v * v;
    __shared__ float sh1[8], sh2[8];
#pragma unroll
    for (int o = 16; o; o >>= 1) {
        s  += __shfl_xor_sync(0xffffffffu, s, o);
        s2 += __shfl_xor_sync(0xffffffffu, s2, o);
    }
    if ((c & 31) == 0) { sh1[c >> 5] = s; sh2[c >> 5] = s2; }
    __syncthreads();
    float S = 0.f, Q = 0.f;
#pragma unroll
    for (int i = 0; i < 8; i++) { S += sh1[i]; Q += sh2[i]; }
    float mean = S * (1.f / C_);
    float var  = Q * (1.f / C_) - mean * mean;
    float r = (v - mean) * rsqrtf(var + EPS_) * w[c] + b[c];
    size_t o = (size_t)row * C_ + c;
    __nv_bfloat16 hi = __float2bfloat16(r);
    outH[o] = hi;
    outL[o] = __float2bfloat16(r - __bfloat162float(hi));
}

// ---------------- NLL + loss ----------------
__global__ void nll_kernel(const float* __restrict__ logits, const int* __restrict__ tgt,
                           float* __restrict__ nll) {
    int warp = (blockIdx.x * blockDim.x + threadIdx.x) >> 5;
    int lane = threadIdx.x & 31;
    if (warp >= BT_) return;
    const float* l = logits + (size_t)warp * V_;
    float mx = -INFINITY;
    for (int c = lane; c < V_; c += 32) mx = fmaxf(mx, l[c]);
#pragma unroll
    for (int o = 16; o; o >>= 1) mx = fmaxf(mx, __shfl_xor_sync(0xffffffffu, mx, o));
    float s = 0.f;
    for (int c = lane; c < V_; c += 32) s += __expf(l[c] - mx);
#pragma unroll
    for (int o = 16; o; o >>= 1) s += __shfl_xor_sync(0xffffffffu, s, o);
    if (lane == 0) nll[warp] = -(l[tgt[warp]] - mx - __logf(s));
}
__global__ void reduce_loss_kernel(const float* __restrict__ nll, float* __restrict__ out) {
    __shared__ float sh[256];
    float s = 0.f;
    for (int i = threadIdx.x; i < BT_; i += 256) s += nll[i];
    sh[threadIdx.x] = s;
    __syncthreads();
    for (int st = 128; st; st >>= 1) {
        if (threadIdx.x < st) sh[threadIdx.x] += sh[threadIdx.x + st];
        __syncthreads();
    }
    if (threadIdx.x == 0) *out = sh[0] * (1.f / BT_);
}

// ---------------- host driver ----------------
extern "C" void kernel_launch(void* const* d_in, const int* in_sizes, int n_in,
                              void* d_out, int out_size) {
    const int*   idx     = (const int*)  d_in[0];
    const int*   target  = (const int*)  d_in[1];
    const float* tok_emb = (const float*)d_in[2];
    const float* pos_emb = (const float*)d_in[3];
    const float* Wq      = (const float*)d_in[4];
    const float* Wk      = (const float*)d_in[5];
    const float* Wv      = (const float*)d_in[6];
    const float* Wo      = (const float*)d_in[7];
    const float* bo      = (const float*)d_in[8];
    const float* W1      = (const float*)d_in[9];
    const float* b1      = (const float*)d_in[10];
    const float* W2      = (const float*)d_in[11];
    const float* b2_     = (const float*)d_in[12];
    const float* ln1_w   = (const float*)d_in[13];
    const float* ln1_b   = (const float*)d_in[14];
    const float* ln2_w   = (const float*)d_in[15];
    const float* ln2_b   = (const float*)d_in[16];
    const float* lnf_w   = (const float*)d_in[17];
    const float* lnf_b   = (const float*)d_in[18];
    const float* Wlm     = (const float*)d_in[19];
    const float* blm     = (const float*)d_in[20];

    float *px, *pqkv, *pnll;
    __nv_bfloat16 *pxh, *pxl, *pah, *pal, *phh, *phl, *pwh, *pwl;
    cudaGetSymbolAddress((void**)&px,   g_x);
    cudaGetSymbolAddress((void**)&pqkv, g_qkv);
    cudaGetSymbolAddress((void**)&pnll, g_nll);
    cudaGetSymbolAddress((void**)&pxh,  g_xh);
    cudaGetSymbolAddress((void**)&pxl,  g_xl);
    cudaGetSymbolAddress((void**)&pah,  g_ah);
    cudaGetSymbolAddress((void**)&pal,  g_al);
    cudaGetSymbolAddress((void**)&phh,  g_hh);
    cudaGetSymbolAddress((void**)&phl,  g_hl);
    cudaGetSymbolAddress((void**)&pwh,  g_wh);
    cudaGetSymbolAddress((void**)&pwl,  g_wl);

    cudaFuncSetAttribute(flash_attn, cudaFuncAttributeMaxDynamicSharedMemorySize, ATTN_SMEM);
    const int smem256 = 2 * (32768 + 2 * 256 * 128);
    const int smem128 = 2 * (32768 + 2 * 128 * 128);
    cudaFuncSetAttribute(hmma_gemm3<256, 0>, cudaFuncAttributeMaxDynamicSharedMemorySize, smem256);
    cudaFuncSetAttribute(hmma_gemm3<256, 1>, cudaFuncAttributeMaxDynamicSharedMemorySize, smem256);
    cudaFuncSetAttribute(hmma_gemm3<256, 2>, cudaFuncAttributeMaxDynamicSharedMemorySize, smem256);
    cudaFuncSetAttribute(hmma_gemm3<128, 0>, cudaFuncAttributeMaxDynamicSharedMemorySize, smem128);

    convw_all<<<dim3(256, 37), 256>>>(Wq, Wk, Wv, Wo, W1, W2, Wlm, pwh, pwl);
    embed_kernel<<<BT_, C_>>>(idx, tok_emb, pos_emb, px, pxh, pxl);

    const size_t QKV_OSTRIDE = (size_t)BT_ * C_;
    const size_t QKV_WSTRIDE = (size_t)6 * WMAT_ELEMS;

    for (int l = 0; l < L_; l++) {
        hmma_gemm3<256, 0><<<dim3(128, 3), 256, smem256>>>(pxh, pxl,
            pwh + WOFF(0, l), pwl + WOFF(0, l), QKV_WSTRIDE,
            pqkv, QKV_OSTRIDE, nullptr, nullptr, nullptr, nullptr, nullptr, nullptr, C_);
        flash_attn<<<B_ * H_, 256, ATTN_SMEM>>>(pqkv, pah, pal);
        hmma_gemm3<256, 2><<<dim3(128, 1), 256, smem256>>>(pah, pal,
            pwh + WOFF(3, l), pwl + WOFF(3, l), 0,
            px, 0, pxh, pxl, bo + l * C_, px, ln1_w + l * C_, ln1_b + l * C_, C_);
        hmma_gemm3<256, 1><<<dim3(128, 1), 256, smem256>>>(pxh, pxl,
            pwh + WOFF(4, l), pwl + WOFF(4, l), 0,
            nullptr, 0, phh, phl, b1 + l * C_, nullptr, nullptr, nullptr, C_);
        hmma_gemm3<256, 2><<<dim3(128, 1), 256, smem256>>>(phh, phl,
            pwh + WOFF(5, l), pwl + WOFF(5, l), 0,
            px, 0, pxh, pxl, b2_ + l * C_, px, ln2_w + l * C_, ln2_b + l * C_, C_);
    }
    add_ln_kernel<<<BT_, C_>>>(px, lnf_w, lnf_b, pxh, pxl);

    float* logits = (out_size >= BT_ * V_) ? (float*)d_out : pqkv;
    hmma_gemm3<128, 0><<<dim3(128, 1), 256, smem128>>>(pxh, pxl,
        pwh + WOFF_LM, pwl + WOFF_LM, 0,
        logits, 0, nullptr, nullptr, blm, nullptr, nullptr, nullptr, V_);

    nll_kernel<<<(BT_ * 32 + 255) / 256, 256>>>(logits, target, pnll);

    float* loss_dst = nullptr;
    if (out_size == 1)            loss_dst = (float*)d_out;
    else if (out_size > BT_ * V_) loss_dst = (float*)d_out + BT_ * V_;
    if (loss_dst) reduce_loss_kernel<<<1, 256>>>(pnll, loss_dst);
}